// round 12
// baseline (speedup 1.0000x reference)
#include <cuda_runtime.h>
#include <cuda_bf16.h>
#include <cuda_fp16.h>
#include <math.h>
#include <stdint.h>

#define B_    4
#define NC_   4096
#define NS_   1024
#define CD_   1024
#define SD_   768
#define H_    16
#define D_    64
#define INNER_ 1024
#define LN_EPS 1e-5f

// ---------------- static device scratch ----------------
__device__ float g_attn[(size_t)B_ * H_ * NC_ * NS_];   // probs fp16 rows (2048 B/row used)
__device__ float g_x[(size_t)B_ * NC_ * CD_];
__device__ float g_v[(size_t)B_ * NS_ * INNER_];

__device__ __nv_bfloat16 g_c_hi[(size_t)B_ * NC_ * CD_];
__device__ __nv_bfloat16 g_c_lo[(size_t)B_ * NC_ * CD_];
__device__ __nv_bfloat16 g_s_hi[(size_t)B_ * NS_ * SD_];
__device__ __nv_bfloat16 g_s_lo[(size_t)B_ * NS_ * SD_];
__device__ __nv_bfloat16 g_qh[(size_t)B_ * NC_ * INNER_];   // Q (pre-scaled 1/8) hi/lo
__device__ __nv_bfloat16 g_ql[(size_t)B_ * NC_ * INNER_];
__device__ __nv_bfloat16 g_kh[(size_t)B_ * NS_ * INNER_];
__device__ __nv_bfloat16 g_kl[(size_t)B_ * NS_ * INNER_];
__device__ __half        g_vth[(size_t)B_ * INNER_ * NS_];  // V^T per head [z*64+d][s], fp16
__device__ __nv_bfloat16 g_avh[(size_t)B_ * NC_ * INNER_];  // attended, bf16

__device__ __nv_bfloat16 g_wqt_hi[INNER_ * CD_];
__device__ __nv_bfloat16 g_wqt_lo[INNER_ * CD_];
__device__ __nv_bfloat16 g_wkt_hi[INNER_ * SD_];
__device__ __nv_bfloat16 g_wkt_lo[INNER_ * SD_];
__device__ __nv_bfloat16 g_wvt_hi[INNER_ * SD_];
__device__ __nv_bfloat16 g_wvt_lo[INNER_ * SD_];
__device__ __nv_bfloat16 g_wot_hi[CD_ * INNER_];

// ================= helpers =================
__device__ __forceinline__ uint32_t smem_u32(const void* p) {
    uint32_t a;
    asm("{ .reg .u64 t; cvta.to.shared.u64 t, %1; cvt.u32.u64 %0, t; }" : "=r"(a) : "l"(p));
    return a;
}
__device__ __forceinline__ void ldsm_x4(uint32_t* f, uint32_t addr) {
    asm volatile("ldmatrix.sync.aligned.m8n8.x4.shared.b16 {%0,%1,%2,%3}, [%4];"
                 : "=r"(f[0]), "=r"(f[1]), "=r"(f[2]), "=r"(f[3]) : "r"(addr));
}
__device__ __forceinline__ void ldsm_x2(uint32_t* f, uint32_t addr) {
    asm volatile("ldmatrix.sync.aligned.m8n8.x2.shared.b16 {%0,%1}, [%2];"
                 : "=r"(f[0]), "=r"(f[1]) : "r"(addr));
}
__device__ __forceinline__ void mma_bf16(float* c, const uint32_t* a, const uint32_t* b) {
    asm volatile("mma.sync.aligned.m16n8k16.row.col.f32.bf16.bf16.f32 "
                 "{%0,%1,%2,%3}, {%4,%5,%6,%7}, {%8,%9}, {%0,%1,%2,%3};"
                 : "+f"(c[0]), "+f"(c[1]), "+f"(c[2]), "+f"(c[3])
                 : "r"(a[0]), "r"(a[1]), "r"(a[2]), "r"(a[3]), "r"(b[0]), "r"(b[1]));
}
__device__ __forceinline__ void mma_f16(float* c, const uint32_t* a, const uint32_t* b) {
    asm volatile("mma.sync.aligned.m16n8k16.row.col.f32.f16.f16.f32 "
                 "{%0,%1,%2,%3}, {%4,%5,%6,%7}, {%8,%9}, {%0,%1,%2,%3};"
                 : "+f"(c[0]), "+f"(c[1]), "+f"(c[2]), "+f"(c[3])
                 : "r"(a[0]), "r"(a[1]), "r"(a[2]), "r"(a[3]), "r"(b[0]), "r"(b[1]));
}
__device__ __forceinline__ void split2(float x, float y, uint32_t& hp, uint32_t& lp) {
    __nv_bfloat16 hx = __float2bfloat16(x), hy = __float2bfloat16(y);
    hp = ((uint32_t)*(uint16_t*)&hy << 16) | *(uint16_t*)&hx;
    __nv_bfloat16 lx = __float2bfloat16(x - __bfloat162float(hx));
    __nv_bfloat16 ly = __float2bfloat16(y - __bfloat162float(hy));
    lp = ((uint32_t)*(uint16_t*)&ly << 16) | *(uint16_t*)&lx;
}
__device__ __forceinline__ uint32_t pack2(float x, float y) {
    __nv_bfloat16 hx = __float2bfloat16(x), hy = __float2bfloat16(y);
    return ((uint32_t)*(uint16_t*)&hy << 16) | *(uint16_t*)&hx;
}
__device__ __forceinline__ uint32_t packh2(float x, float y) {
    __half2 t = __floats2half2_rn(x, y);
    return *(uint32_t*)&t;
}

// ================================================================
// Templated bf16-split GEMM (validated R9). TERMS=3 or 1.
// ================================================================
#define TILE_B   10240
#define BUF_B    (4 * TILE_B)
#define GSMEM_B  (2 * BUF_B)

template <int TERMS>
__global__ void __launch_bounds__(256, 1) gemm_mma(
    const __nv_bfloat16* __restrict__ Ah, const __nv_bfloat16* __restrict__ Al,
    const __nv_bfloat16* __restrict__ Bh, const __nv_bfloat16* __restrict__ Bl,
    float* __restrict__ C, __nv_bfloat16* __restrict__ Oh, __nv_bfloat16* __restrict__ Ol,
    int M, int N, int K,
    const float* __restrict__ bias, const float* __restrict__ resid, float alpha)
{
    extern __shared__ char sm[];
    const int tid = threadIdx.x;
    const int lane = tid & 31;
    const int wid = tid >> 5;
    const int bm = blockIdx.y * 128;
    const int bn = blockIdx.x * 128;
    const int nch = K >> 5;
    const int NIT = (TERMS == 3) ? 8 : 4;

    const int wm = (wid >> 2) * 64;
    const int wn = (wid & 3) * 32;

    const uint32_t sA = smem_u32(sm);
    const uint32_t a_off = (uint32_t)(lane & 15) * 80 + (uint32_t)(lane >> 4) * 16;
    const uint32_t b_off = (uint32_t)(lane & 7) * 80 + (uint32_t)((lane >> 3) & 1) * 16;

    float acc[4][4][4];
#pragma unroll
    for (int mt = 0; mt < 4; mt++)
#pragma unroll
        for (int nt = 0; nt < 4; nt++)
#pragma unroll
            for (int r = 0; r < 4; r++) acc[mt][nt][r] = 0.f;

#pragma unroll
    for (int it = 0; it < NIT; it++) {
        const int idx = (it << 8) + tid;
        const int t = (TERMS == 3) ? (idx >> 9) : ((idx >> 9) * 2);
        const int r = (idx >> 2) & 127;
        const int s = idx & 3;
        const __nv_bfloat16* src = (t == 0) ? Ah : (t == 1) ? Al : (t == 2) ? Bh : Bl;
        const int rb = (t < 2) ? bm : bn;
        uint4 v = *(const uint4*)(src + (size_t)(rb + r) * K + s * 8);
        *(uint4*)(sm + t * TILE_B + r * 80 + s * 16) = v;
    }
    __syncthreads();

    for (int c = 0; c < nch; c++) {
        uint4 g[8];
        if (c + 1 < nch) {
            const int ko = (c + 1) << 5;
#pragma unroll
            for (int it = 0; it < NIT; it++) {
                const int idx = (it << 8) + tid;
                const int t = (TERMS == 3) ? (idx >> 9) : ((idx >> 9) * 2);
                const int r = (idx >> 2) & 127;
                const int s = idx & 3;
                const __nv_bfloat16* src = (t == 0) ? Ah : (t == 1) ? Al : (t == 2) ? Bh : Bl;
                const int rb = (t < 2) ? bm : bn;
                g[it] = *(const uint4*)(src + (size_t)(rb + r) * K + ko + s * 8);
            }
        }
        {
            const uint32_t base = sA + (uint32_t)(c & 1) * BUF_B;
#pragma unroll
            for (int kk = 0; kk < 2; kk++) {
                const uint32_t ko = kk * 32;
                uint32_t bh[4][2], bl[4][2];
#pragma unroll
                for (int nt = 0; nt < 4; nt++) {
                    ldsm_x2(bh[nt], base + 2 * TILE_B + (uint32_t)(wn + nt * 8) * 80 + b_off + ko);
                    if (TERMS == 3)
                        ldsm_x2(bl[nt], base + 3 * TILE_B + (uint32_t)(wn + nt * 8) * 80 + b_off + ko);
                }
#pragma unroll
                for (int mt = 0; mt < 4; mt++) {
                    uint32_t ah[4], al[4];
                    ldsm_x4(ah, base + (uint32_t)(wm + mt * 16) * 80 + a_off + ko);
                    if (TERMS == 3)
                        ldsm_x4(al, base + TILE_B + (uint32_t)(wm + mt * 16) * 80 + a_off + ko);
#pragma unroll
                    for (int nt = 0; nt < 4; nt++) {
                        mma_bf16(acc[mt][nt], ah, bh[nt]);
                        if (TERMS == 3) {
                            mma_bf16(acc[mt][nt], ah, bl[nt]);
                            mma_bf16(acc[mt][nt], al, bh[nt]);
                        }
                    }
                }
            }
        }
        if (c + 1 < nch) {
            char* dst = sm + ((c + 1) & 1) * BUF_B;
#pragma unroll
            for (int it = 0; it < NIT; it++) {
                const int idx = (it << 8) + tid;
                const int t = (TERMS == 3) ? (idx >> 9) : ((idx >> 9) * 2);
                const int r = (idx >> 2) & 127;
                const int s = idx & 3;
                *(uint4*)(dst + t * TILE_B + r * 80 + s * 16) = g[it];
            }
        }
        __syncthreads();
    }

#pragma unroll
    for (int mt = 0; mt < 4; mt++) {
        const int row0 = bm + wm + mt * 16 + (lane >> 2);
#pragma unroll
        for (int nt = 0; nt < 4; nt++) {
            const int col = bn + wn + nt * 8 + (lane & 3) * 2;
#pragma unroll
            for (int half = 0; half < 2; half++) {
                const int row = row0 + half * 8;
                float vx = acc[mt][nt][half * 2] * alpha;
                float vy = acc[mt][nt][half * 2 + 1] * alpha;
                if (Oh) {
                    uint32_t hp, lp;
                    split2(vx, vy, hp, lp);
                    *(uint32_t*)(Oh + (size_t)row * N + col) = hp;
                    *(uint32_t*)(Ol + (size_t)row * N + col) = lp;
                } else {
                    if (bias) { vx += bias[col]; vy += bias[col + 1]; }
                    if (resid) {
                        float2 t = *(const float2*)(resid + (size_t)row * N + col);
                        vx += t.x; vy += t.y;
                    }
                    *(float2*)(C + (size_t)row * N + col) = make_float2(vx, vy);
                }
            }
        }
    }
}

// ================================================================
// FUSED scores + softmax + P·V.  512 THREADS (16 warps) this round.
// per CTA = (z, 32 q rows), NS=1024. Same smem layout as R11.
// Phase 1: 16 warps = 2M x 8N (warp tile 16x16).
// Phase 2: 2 rows per warp.
// Phase 3: 16 warps = 2M x 8N over O(32x64) (warp tile 16x8).
// ================================================================
#define FS_QSP  4608
#define FS_QT   (2 * FS_QSP)
#define FS_KSP  18432
#define FS_KT   (2 * FS_KSP)
#define FS_SROW 4128
#define FS_SMEM (FS_QT + 2 * FS_KT + 32 * FS_SROW)   // 215040

__global__ void __launch_bounds__(512, 1) fused_attn()
{
    extern __shared__ char sm[];
    const int tid = threadIdx.x;
    const int lane = tid & 31;
    const int wid = tid >> 5;           // 0..15
    const int z = blockIdx.y;
    const int b = z >> 4;
    const int h = z & 15;
    const int q0 = b * NC_ + blockIdx.x * 32;
    const int kb = b * NS_;

    char* smQ = sm;
    char* smK = sm + FS_QT;
    char* smS = sm + FS_QT + 2 * FS_KT;
    const uint32_t uQ = smem_u32(smQ);
    const uint32_t uK = smem_u32(smK);
    const uint32_t uS = smem_u32(smS);

    // ---- Phase 1 loads: Q tile (512 items, 1 iter), K chunk 0 (2048 items, 4 iters) ----
    {
        const int idx = tid;
        const int sp = idx >> 8;
        const int r = (idx >> 3) & 31;
        const int s = idx & 7;
        const __nv_bfloat16* src = sp ? g_ql : g_qh;
        uint4 v = *(const uint4*)(src + (size_t)(q0 + r) * INNER_ + h * 64 + s * 8);
        *(uint4*)(smQ + sp * FS_QSP + r * 144 + s * 16) = v;
    }
#pragma unroll
    for (int it = 0; it < 4; it++) {
        const int idx = (it << 9) + tid;
        const int sp = idx >> 10;
        const int r = (idx >> 3) & 127;
        const int s = idx & 7;
        const __nv_bfloat16* src = sp ? g_kl : g_kh;
        uint4 v = *(const uint4*)(src + (size_t)(kb + r) * INNER_ + h * 64 + s * 8);
        *(uint4*)(smK + sp * FS_KSP + r * 144 + s * 16) = v;
    }
    __syncthreads();

    const int wm = (wid >> 3) * 16;     // 0 / 16
    const int wn = (wid & 7) * 16;      // 0..112
    const uint32_t a_off = (uint32_t)(lane & 15) * 144 + (uint32_t)(lane >> 4) * 16;
    const uint32_t b_off = (uint32_t)(lane & 7) * 144 + (uint32_t)((lane >> 3) & 1) * 16;

    for (int kc = 0; kc < 8; kc++) {
        uint4 g[4];
        if (kc + 1 < 8) {
            const int krow = kb + (kc + 1) * 128;
#pragma unroll
            for (int it = 0; it < 4; it++) {
                const int idx = (it << 9) + tid;
                const int sp = idx >> 10;
                const int r = (idx >> 3) & 127;
                const int s = idx & 7;
                const __nv_bfloat16* src = sp ? g_kl : g_kh;
                g[it] = *(const uint4*)(src + (size_t)(krow + r) * INNER_ + h * 64 + s * 8);
            }
        }
        float acc[2][4];
#pragma unroll
        for (int nt = 0; nt < 2; nt++)
#pragma unroll
            for (int r = 0; r < 4; r++) acc[nt][r] = 0.f;

        const uint32_t kbuf = uK + (uint32_t)(kc & 1) * FS_KT;
#pragma unroll
        for (int kk = 0; kk < 4; kk++) {
            const uint32_t ko = kk * 32;
            uint32_t ah[4], al[4];
            ldsm_x4(ah, uQ + (uint32_t)wm * 144 + a_off + ko);
            ldsm_x4(al, uQ + FS_QSP + (uint32_t)wm * 144 + a_off + ko);
            uint32_t bh[2][2], bl[2][2];
#pragma unroll
            for (int nt = 0; nt < 2; nt++) {
                ldsm_x2(bh[nt], kbuf + (uint32_t)(wn + nt * 8) * 144 + b_off + ko);
                ldsm_x2(bl[nt], kbuf + FS_KSP + (uint32_t)(wn + nt * 8) * 144 + b_off + ko);
            }
#pragma unroll
            for (int nt = 0; nt < 2; nt++) {
                mma_bf16(acc[nt], ah, bh[nt]);
                mma_bf16(acc[nt], ah, bl[nt]);
                mma_bf16(acc[nt], al, bh[nt]);
            }
        }
#pragma unroll
        for (int nt = 0; nt < 2; nt++) {
            const int col = kc * 128 + wn + nt * 8 + (lane & 3) * 2;
#pragma unroll
            for (int half = 0; half < 2; half++) {
                const int row = wm + (lane >> 2) + half * 8;
                *(float2*)(smS + row * FS_SROW + col * 4) =
                    make_float2(acc[nt][half * 2], acc[nt][half * 2 + 1]);
            }
        }
        if (kc + 1 < 8) {
            char* dst = smK + ((kc + 1) & 1) * FS_KT;
#pragma unroll
            for (int it = 0; it < 4; it++) {
                const int idx = (it << 9) + tid;
                const int sp = idx >> 10;
                const int r = (idx >> 3) & 127;
                const int s = idx & 7;
                *(uint4*)(dst + sp * FS_KSP + r * 144 + s * 16) = g[it];
            }
        }
        __syncthreads();
    }

    // ---- Phase 2: softmax; 2 rows per warp; probs fp16 -> smem + global ----
    char* gz = (char*)g_attn + (((size_t)z << 12) + (size_t)blockIdx.x * 32) * 2048;
#pragma unroll
    for (int rr = 0; rr < 2; rr++) {
        const int r = wid * 2 + rr;
        char* rb = smS + r * FS_SROW;
        float4 v[8];
#pragma unroll
        for (int it = 0; it < 8; it++) v[it] = *(const float4*)(rb + lane * 16 + it * 512);

        float m = -1e30f;
#pragma unroll
        for (int it = 0; it < 8; it++)
            m = fmaxf(m, fmaxf(fmaxf(v[it].x, v[it].y), fmaxf(v[it].z, v[it].w)));
#pragma unroll
        for (int o = 16; o; o >>= 1) m = fmaxf(m, __shfl_xor_sync(0xffffffffu, m, o));

        float s = 0.f;
#pragma unroll
        for (int it = 0; it < 8; it++) {
            v[it].x = __expf(v[it].x - m); v[it].y = __expf(v[it].y - m);
            v[it].z = __expf(v[it].z - m); v[it].w = __expf(v[it].w - m);
            s += (v[it].x + v[it].y) + (v[it].z + v[it].w);
        }
#pragma unroll
        for (int o = 16; o; o >>= 1) s += __shfl_xor_sync(0xffffffffu, s, o);
        const float inv = 1.f / s;

        char* grow = gz + (size_t)r * 2048;
#pragma unroll
        for (int it = 0; it < 8; it++) {
            uint2 p = make_uint2(packh2(v[it].x * inv, v[it].y * inv),
                                 packh2(v[it].z * inv, v[it].w * inv));
            const int cofs = (it * 128 + lane * 4) * 2;
            *(uint2*)(rb + cofs) = p;       // own smem row (first 2048 B)
            *(uint2*)(grow + cofs) = p;     // global
        }
    }
    __syncthreads();

    // ---- Phase 3: O = P @ V^T  (64-k chunks, av_mma-validated layout) ----
    const __half* vth = g_vth + (size_t)z * 64 * NS_;
    const int wm3 = (wid >> 3) * 16;    // 0 / 16
    const int wd = (wid & 7) * 8;       // 0..56
    const uint32_t ap_off = (uint32_t)(lane & 15) * FS_SROW + (uint32_t)(lane >> 4) * 16;

    float acco[4];
#pragma unroll
    for (int r = 0; r < 4; r++) acco[r] = 0.f;

    // V chunk: 64 rows x 64 fp16 (128 B) -> 512 uint4 items, 1 iteration @512 thr
#define FV_LOAD(c_, g_)                                                               \
    {                                                                                 \
        const int r = tid >> 3;                                                       \
        const int s = tid & 7;                                                        \
        g_ = *(const uint4*)(vth + (size_t)r * NS_ + (c_) * 64 + s * 8);              \
    }
#define FV_STORE(buf_, g_)                                                            \
    {                                                                                 \
        const int r = tid >> 3;                                                       \
        const int s = tid & 7;                                                        \
        *(uint4*)(smK + (buf_) * FS_KT + r * 144 + s * 16) = g_;                      \
    }

    {
        uint4 g;
        FV_LOAD(0, g);
        FV_STORE(0, g);
    }
    __syncthreads();

    for (int c = 0; c < 16; c++) {
        uint4 g;
        if (c + 1 < 16) FV_LOAD(c + 1, g);
        {
            const uint32_t vbuf = uK + (uint32_t)(c & 1) * FS_KT;
#pragma unroll
            for (int kk = 0; kk < 4; kk++) {
                const uint32_t ko = kk * 32;   // 16 fp16 = 32 B
                uint32_t ah[4];
                ldsm_x4(ah, uS + (uint32_t)wm3 * FS_SROW + ap_off + (uint32_t)c * 128 + ko);
                uint32_t bh[2];
                ldsm_x2(bh, vbuf + (uint32_t)wd * 144 + b_off + ko);
                mma_f16(acco, ah, bh);
            }
        }
        if (c + 1 < 16) FV_STORE((c + 1) & 1, g);
        __syncthreads();
    }

    // epilogue: O 32x64 -> g_avh bf16
    {
        const int col = h * 64 + wd + (lane & 3) * 2;
#pragma unroll
        for (int half = 0; half < 2; half++) {
            const int row = q0 + wm3 + (lane >> 2) + half * 8;
            *(uint32_t*)(g_avh + (size_t)row * INNER_ + col) =
                pack2(acco[half * 2], acco[half * 2 + 1]);
        }
    }
}

// ================================================================
// attn_mean from fp16 probs (2048 B rows)
// ================================================================
__global__ void attn_mean_kernel(float* __restrict__ out2)
{
    const size_t idx = (size_t)blockIdx.x * 256 + threadIdx.x;
    const size_t e0 = idx << 2;
    const int b = (int)(e0 >> 22);
    const int q = (int)((e0 >> 10) & 4095);
    const int k = (int)(e0 & 1023);
    const __half* pb = (const __half*)g_attn;

    float s0 = 0.f, s1 = 0.f, s2 = 0.f, s3 = 0.f;
#pragma unroll
    for (int h = 0; h < H_; h++) {
        const size_t row = ((size_t)(b * H_ + h) << 12) + q;
        uint2 hv = *(const uint2*)(pb + row * 1024 + k);
        float2 h0 = __half22float2(*(__half2*)&hv.x);
        float2 h1 = __half22float2(*(__half2*)&hv.y);
        s0 += h0.x; s1 += h0.y; s2 += h1.x; s3 += h1.y;
    }
    const float c = 1.0f / 16.0f;
    *(float4*)(out2 + e0) = make_float4(s0 * c, s1 * c, s2 * c, s3 * c);
}

// ================================================================
// fp32 -> bf16 hi/lo split
// ================================================================
__global__ void split_kernel(const float4* __restrict__ in,
                             uint2* __restrict__ oh, uint2* __restrict__ ol, int n4)
{
    const int i = blockIdx.x * 256 + threadIdx.x;
    if (i >= n4) return;
    float4 v = in[i];
    __align__(8) __nv_bfloat16 h[4], l[4];
    const float f[4] = {v.x, v.y, v.z, v.w};
#pragma unroll
    for (int j = 0; j < 4; j++) {
        h[j] = __float2bfloat16(f[j]);
        l[j] = __float2bfloat16(f[j] - __bfloat162float(h[j]));
    }
    oh[i] = *(uint2*)h;
    ol[i] = *(uint2*)l;
}

// ================================================================
// Transpose + split weights: fp32 [R][Ncol] -> bf16 [Ncol][R] hi/lo
// ================================================================
__global__ void tsplit_kernel(const float* __restrict__ in,
                              __nv_bfloat16* __restrict__ oh,
                              __nv_bfloat16* __restrict__ ol, int R, int Ncol)
{
    __shared__ float t[32][33];
    const int bx = blockIdx.x * 32, by = blockIdx.y * 32;
    const int tx = threadIdx.x, ty = threadIdx.y;
#pragma unroll
    for (int i = 0; i < 32; i += 8)
        t[ty + i][tx] = in[(size_t)(by + ty + i) * Ncol + bx + tx];
    __syncthreads();
#pragma unroll
    for (int i = 0; i < 32; i += 8) {
        const float v = t[tx][ty + i];
        const size_t o = (size_t)(bx + ty + i) * R + by + tx;
        __nv_bfloat16 h = __float2bfloat16(v);
        oh[o] = h;
        ol[o] = __float2bfloat16(v - __bfloat162float(h));
    }
}

// ================================================================
// V^T to fp16
// ================================================================
__global__ void vtsplit_kernel()
{
    __shared__ float t[32][33];
    const int b = blockIdx.z;
    const int bx = blockIdx.x * 32;
    const int by = blockIdx.y * 32;
    const int tx = threadIdx.x, ty = threadIdx.y;
    const float* in = g_v + (size_t)b * NS_ * INNER_;
#pragma unroll
    for (int i = 0; i < 32; i += 8)
        t[ty + i][tx] = in[(size_t)(by + ty + i) * INNER_ + bx + tx];
    __syncthreads();
#pragma unroll
    for (int i = 0; i < 32; i += 8) {
        const float v = t[tx][ty + i];
        g_vth[(size_t)(b * 1024 + bx + ty + i) * NS_ + by + tx] = __float2half_rn(v);
    }
}

// ================================================================
// LayerNorm
// ================================================================
__global__ void ln_kernel(const float* __restrict__ gamma,
                          const float* __restrict__ beta,
                          float* __restrict__ out)
{
    __shared__ float reds[9];
    __shared__ float redq[9];
    const size_t row = blockIdx.x;
    const int tid = threadIdx.x;

    float4 x = reinterpret_cast<const float4*>(g_x + row * CD_)[tid];
    float s = x.x + x.y + x.z + x.w;
    float q = x.x * x.x + x.y * x.y + x.z * x.z + x.w * x.w;
#pragma unroll
    for (int o = 16; o; o >>= 1) {
        s += __shfl_xor_sync(0xffffffffu, s, o);
        q += __shfl_xor_sync(0xffffffffu, q, o);
    }
    if ((tid & 31) == 0) { reds[tid >> 5] = s; redq[tid >> 5] = q; }
    __syncthreads();
    if (tid == 0) {
        float ss = 0.f, qq = 0.f;
#pragma unroll
        for (int i = 0; i < 8; i++) { ss += reds[i]; qq += redq[i]; }
        reds[8] = ss; redq[8] = qq;
    }
    __syncthreads();
    const float mu = reds[8] * (1.0f / 1024.0f);
    const float var = redq[8] * (1.0f / 1024.0f) - mu * mu;
    const float rstd = rsqrtf(var + LN_EPS);

    float4 g = reinterpret_cast<const float4*>(gamma)[tid];
    float4 bb = reinterpret_cast<const float4*>(beta)[tid];
    float4 r;
    r.x = (x.x - mu) * rstd * g.x + bb.x;
    r.y = (x.y - mu) * rstd * g.y + bb.y;
    r.z = (x.z - mu) * rstd * g.z + bb.z;
    r.w = (x.w - mu) * rstd * g.w + bb.w;
    reinterpret_cast<float4*>(out + row * CD_)[tid] = r;
}

// ================================================================
extern "C" void kernel_launch(void* const* d_in, const int* in_sizes, int n_in,
                              void* d_out, int out_size)
{
    const float* content = (const float*)d_in[0];
    const float* style   = (const float*)d_in[1];
    const float* Wq      = (const float*)d_in[2];
    const float* Wk      = (const float*)d_in[3];
    const float* Wv      = (const float*)d_in[4];
    const float* Wo      = (const float*)d_in[5];
    const float* bo      = (const float*)d_in[6];
    const float* gamma   = (const float*)d_in[7];
    const float* beta    = (const float*)d_in[8];
    float* out = (float*)d_out;
    float* out_attn = out + (size_t)B_ * NC_ * CD_;

    cudaFuncSetAttribute(gemm_mma<3>, cudaFuncAttributeMaxDynamicSharedMemorySize, GSMEM_B);
    cudaFuncSetAttribute(gemm_mma<1>, cudaFuncAttributeMaxDynamicSharedMemorySize, GSMEM_B);
    cudaFuncSetAttribute(fused_attn, cudaFuncAttributeMaxDynamicSharedMemorySize, FS_SMEM);

    float *p_x, *p_v;
    __nv_bfloat16 *p_chi, *p_clo, *p_shi, *p_slo, *p_avh;
    __nv_bfloat16 *p_qh, *p_ql, *p_kh, *p_kl;
    __nv_bfloat16 *p_wqh, *p_wql, *p_wkh, *p_wkl, *p_wvh, *p_wvl, *p_woh;
    cudaGetSymbolAddress((void**)&p_v,   g_v);
    cudaGetSymbolAddress((void**)&p_x,   g_x);
    cudaGetSymbolAddress((void**)&p_chi, g_c_hi);
    cudaGetSymbolAddress((void**)&p_clo, g_c_lo);
    cudaGetSymbolAddress((void**)&p_shi, g_s_hi);
    cudaGetSymbolAddress((void**)&p_slo, g_s_lo);
    cudaGetSymbolAddress((void**)&p_qh,  g_qh);
    cudaGetSymbolAddress((void**)&p_ql,  g_ql);
    cudaGetSymbolAddress((void**)&p_kh,  g_kh);
    cudaGetSymbolAddress((void**)&p_kl,  g_kl);
    cudaGetSymbolAddress((void**)&p_avh, g_avh);
    cudaGetSymbolAddress((void**)&p_wqh, g_wqt_hi);
    cudaGetSymbolAddress((void**)&p_wql, g_wqt_lo);
    cudaGetSymbolAddress((void**)&p_wkh, g_wkt_hi);
    cudaGetSymbolAddress((void**)&p_wkl, g_wkt_lo);
    cudaGetSymbolAddress((void**)&p_wvh, g_wvt_hi);
    cudaGetSymbolAddress((void**)&p_wvl, g_wvt_lo);
    cudaGetSymbolAddress((void**)&p_woh, g_wot_hi);

    // 0) splits
    split_kernel<<<(B_ * NC_ * CD_ / 4 + 255) / 256, 256>>>(
        (const float4*)content, (uint2*)p_chi, (uint2*)p_clo, B_ * NC_ * CD_ / 4);
    split_kernel<<<(B_ * NS_ * SD_ / 4 + 255) / 256, 256>>>(
        (const float4*)style, (uint2*)p_shi, (uint2*)p_slo, B_ * NS_ * SD_ / 4);
    tsplit_kernel<<<dim3(32, 32), dim3(32, 8)>>>(Wq, p_wqh, p_wql, CD_, INNER_);
    tsplit_kernel<<<dim3(32, 24), dim3(32, 8)>>>(Wk, p_wkh, p_wkl, SD_, INNER_);
    tsplit_kernel<<<dim3(32, 24), dim3(32, 8)>>>(Wv, p_wvh, p_wvl, SD_, INNER_);
    // Wo: only hi needed (1-term O-proj). lo lands in g_ql, overwritten by Q proj after.
    tsplit_kernel<<<dim3(32, 32), dim3(32, 8)>>>(Wo, p_woh, p_ql /*discard*/, INNER_, CD_);

    // 1) Q proj -> bf16 hi/lo (pre-scaled 1/8)
    gemm_mma<3><<<dim3(INNER_ / 128, B_ * NC_ / 128), 256, GSMEM_B>>>(
        p_chi, p_clo, p_wqh, p_wql, nullptr, p_qh, p_ql,
        B_ * NC_, INNER_, CD_, nullptr, nullptr, 0.125f);
    // 2) K proj -> bf16 hi/lo
    gemm_mma<3><<<dim3(INNER_ / 128, B_ * NS_ / 128), 256, GSMEM_B>>>(
        p_shi, p_slo, p_wkh, p_wkl, nullptr, p_kh, p_kl,
        B_ * NS_, INNER_, SD_, nullptr, nullptr, 1.0f);
    // 3) V proj -> fp32, then per-head transpose to fp16
    gemm_mma<3><<<dim3(INNER_ / 128, B_ * NS_ / 128), 256, GSMEM_B>>>(
        p_shi, p_slo, p_wvh, p_wvl, p_v, nullptr, nullptr,
        B_ * NS_, INNER_, SD_, nullptr, nullptr, 1.0f);
    vtsplit_kernel<<<dim3(32, 32, B_), dim3(32, 8)>>>();

    // 4) FUSED scores + softmax + P·V (512 threads)
    fused_attn<<<dim3(NC_ / 32, B_ * H_), 512, FS_SMEM>>>();
    // 5) head-mean -> second output
    attn_mean_kernel<<<B_ * NC_ * NS_ / 4 / 256, 256>>>(out_attn);
    // 6) O proj (1-term) + bias + residual
    gemm_mma<1><<<dim3(CD_ / 128, B_ * NC_ / 128), 256, GSMEM_B>>>(
        p_avh, nullptr, p_woh, nullptr, p_x, nullptr, nullptr,
        B_ * NC_, CD_, INNER_, bo, content, 1.0f);
    // 7) LayerNorm -> first output
    ln_kernel<<<B_ * NC_, 256>>>(gamma, beta, out);
}

// round 13
// speedup vs baseline: 1.0688x; 1.0688x over previous
#include <cuda_runtime.h>
#include <cuda_bf16.h>
#include <cuda_fp16.h>
#include <math.h>
#include <stdint.h>

#define B_    4
#define NC_   4096
#define NS_   1024
#define CD_   1024
#define SD_   768
#define H_    16
#define D_    64
#define INNER_ 1024
#define LN_EPS 1e-5f

// ---------------- static device scratch ----------------
__device__ float g_attn[(size_t)B_ * H_ * NC_ * NS_];   // probs fp16 rows (2048 B/row used)
__device__ float g_x[(size_t)B_ * NC_ * CD_];
__device__ float g_v[(size_t)B_ * NS_ * INNER_];

__device__ __nv_bfloat16 g_c_hi[(size_t)B_ * NC_ * CD_];
__device__ __nv_bfloat16 g_c_lo[(size_t)B_ * NC_ * CD_];
__device__ __nv_bfloat16 g_s_hi[(size_t)B_ * NS_ * SD_];
__device__ __nv_bfloat16 g_s_lo[(size_t)B_ * NS_ * SD_];
__device__ __nv_bfloat16 g_qh[(size_t)B_ * NC_ * INNER_];   // Q (pre-scaled 1/8) hi/lo
__device__ __nv_bfloat16 g_ql[(size_t)B_ * NC_ * INNER_];
__device__ __nv_bfloat16 g_kh[(size_t)B_ * NS_ * INNER_];
__device__ __nv_bfloat16 g_kl[(size_t)B_ * NS_ * INNER_];
__device__ __half        g_vth[(size_t)B_ * INNER_ * NS_];  // V^T per head [z*64+d][s], fp16
__device__ __nv_bfloat16 g_avh[(size_t)B_ * NC_ * INNER_];  // attended, bf16

__device__ __nv_bfloat16 g_wqt_hi[INNER_ * CD_];
__device__ __nv_bfloat16 g_wqt_lo[INNER_ * CD_];
__device__ __nv_bfloat16 g_wkt_hi[INNER_ * SD_];
__device__ __nv_bfloat16 g_wkt_lo[INNER_ * SD_];
__device__ __nv_bfloat16 g_wvt_hi[INNER_ * SD_];
__device__ __nv_bfloat16 g_wvt_lo[INNER_ * SD_];
__device__ __nv_bfloat16 g_wot_hi[CD_ * INNER_];

// ================= helpers =================
__device__ __forceinline__ uint32_t smem_u32(const void* p) {
    uint32_t a;
    asm("{ .reg .u64 t; cvta.to.shared.u64 t, %1; cvt.u32.u64 %0, t; }" : "=r"(a) : "l"(p));
    return a;
}
__device__ __forceinline__ void ldsm_x4(uint32_t* f, uint32_t addr) {
    asm volatile("ldmatrix.sync.aligned.m8n8.x4.shared.b16 {%0,%1,%2,%3}, [%4];"
                 : "=r"(f[0]), "=r"(f[1]), "=r"(f[2]), "=r"(f[3]) : "r"(addr));
}
__device__ __forceinline__ void ldsm_x2(uint32_t* f, uint32_t addr) {
    asm volatile("ldmatrix.sync.aligned.m8n8.x2.shared.b16 {%0,%1}, [%2];"
                 : "=r"(f[0]), "=r"(f[1]) : "r"(addr));
}
__device__ __forceinline__ void mma_bf16(float* c, const uint32_t* a, const uint32_t* b) {
    asm volatile("mma.sync.aligned.m16n8k16.row.col.f32.bf16.bf16.f32 "
                 "{%0,%1,%2,%3}, {%4,%5,%6,%7}, {%8,%9}, {%0,%1,%2,%3};"
                 : "+f"(c[0]), "+f"(c[1]), "+f"(c[2]), "+f"(c[3])
                 : "r"(a[0]), "r"(a[1]), "r"(a[2]), "r"(a[3]), "r"(b[0]), "r"(b[1]));
}
__device__ __forceinline__ void mma_f16(float* c, const uint32_t* a, const uint32_t* b) {
    asm volatile("mma.sync.aligned.m16n8k16.row.col.f32.f16.f16.f32 "
                 "{%0,%1,%2,%3}, {%4,%5,%6,%7}, {%8,%9}, {%0,%1,%2,%3};"
                 : "+f"(c[0]), "+f"(c[1]), "+f"(c[2]), "+f"(c[3])
                 : "r"(a[0]), "r"(a[1]), "r"(a[2]), "r"(a[3]), "r"(b[0]), "r"(b[1]));
}
__device__ __forceinline__ void split2(float x, float y, uint32_t& hp, uint32_t& lp) {
    __nv_bfloat16 hx = __float2bfloat16(x), hy = __float2bfloat16(y);
    hp = ((uint32_t)*(uint16_t*)&hy << 16) | *(uint16_t*)&hx;
    __nv_bfloat16 lx = __float2bfloat16(x - __bfloat162float(hx));
    __nv_bfloat16 ly = __float2bfloat16(y - __bfloat162float(hy));
    lp = ((uint32_t)*(uint16_t*)&ly << 16) | *(uint16_t*)&lx;
}
__device__ __forceinline__ uint32_t pack2(float x, float y) {
    __nv_bfloat16 hx = __float2bfloat16(x), hy = __float2bfloat16(y);
    return ((uint32_t)*(uint16_t*)&hy << 16) | *(uint16_t*)&hx;
}
__device__ __forceinline__ uint32_t packh2(float x, float y) {
    __half2 t = __floats2half2_rn(x, y);
    return *(uint32_t*)&t;
}

#define CP16(dst, src)  asm volatile("cp.async.cg.shared.global [%0], [%1], 16;" :: "r"(dst), "l"(src))
#define CP_COMMIT()     asm volatile("cp.async.commit_group;" ::: "memory")
#define CP_WAIT0()      asm volatile("cp.async.wait_group 0;" ::: "memory")
#define CP_WAIT1()      asm volatile("cp.async.wait_group 1;" ::: "memory")

// ================================================================
// Templated bf16-split GEMM with cp.async staging (2 CTAs/SM).
// TERMS=3: Ah*Bh + Ah*Bl + Al*Bh.  TERMS=1: Ah*Bh only (compact smem).
// 128x128 tile, BK=32, 256 thr = 8 warps (2Mx4N, 64x32 each), dbuf smem.
// ================================================================
#define TILE_B    10240
#define GSMEM3_B  (2 * 4 * TILE_B)   // 81920
#define GSMEM1_B  (2 * 2 * TILE_B)   // 40960

template <int TERMS>
__global__ void __launch_bounds__(256, 2) gemm_mma(
    const __nv_bfloat16* __restrict__ Ah, const __nv_bfloat16* __restrict__ Al,
    const __nv_bfloat16* __restrict__ Bh, const __nv_bfloat16* __restrict__ Bl,
    float* __restrict__ C, __nv_bfloat16* __restrict__ Oh, __nv_bfloat16* __restrict__ Ol,
    int M, int N, int K,
    const float* __restrict__ bias, const float* __restrict__ resid, float alpha)
{
    extern __shared__ char sm[];
    const int tid = threadIdx.x;
    const int lane = tid & 31;
    const int wid = tid >> 5;
    const int bm = blockIdx.y * 128;
    const int bn = blockIdx.x * 128;
    const int nch = K >> 5;
    const int NIT = (TERMS == 3) ? 8 : 4;
    const int NTILES = (TERMS == 3) ? 4 : 2;
    const int BUFT = NTILES * TILE_B;
    const int BOFS = (TERMS == 3) ? 2 * TILE_B : TILE_B;   // Bh tile offset in buffer

    const int wm = (wid >> 2) * 64;
    const int wn = (wid & 3) * 32;

    const uint32_t sA = smem_u32(sm);
    const uint32_t a_off = (uint32_t)(lane & 15) * 80 + (uint32_t)(lane >> 4) * 16;
    const uint32_t b_off = (uint32_t)(lane & 7) * 80 + (uint32_t)((lane >> 3) & 1) * 16;

    float acc[4][4][4];
#pragma unroll
    for (int mt = 0; mt < 4; mt++)
#pragma unroll
        for (int nt = 0; nt < 4; nt++)
#pragma unroll
            for (int r = 0; r < 4; r++) acc[mt][nt][r] = 0.f;

    // cp.async issue of one 32-k chunk into buffer `buf`
    auto issue = [&](int c, int buf) {
        const int ko = c << 5;
#pragma unroll
        for (int it = 0; it < NIT; it++) {
            const int idx = (it << 8) + tid;
            int t, slot;
            if (TERMS == 3) { t = idx >> 9; slot = t; }
            else            { slot = idx >> 9; t = slot * 2; }
            const int r = (idx >> 2) & 127;
            const int s = idx & 3;
            const __nv_bfloat16* src = (t == 0) ? Ah : (t == 1) ? Al : (t == 2) ? Bh : Bl;
            const int rb = (t < 2) ? bm : bn;
            CP16(sA + buf * BUFT + slot * TILE_B + r * 80 + s * 16,
                 src + (size_t)(rb + r) * K + ko + s * 8);
        }
        CP_COMMIT();
    };

    issue(0, 0);

    for (int c = 0; c < nch; c++) {
        if (c + 1 < nch) { issue(c + 1, (c + 1) & 1); CP_WAIT1(); }
        else             { CP_WAIT0(); }
        __syncthreads();

        const uint32_t base = sA + (uint32_t)(c & 1) * BUFT;
#pragma unroll
        for (int kk = 0; kk < 2; kk++) {
            const uint32_t ko = kk * 32;
            uint32_t bh[4][2], bl[4][2];
#pragma unroll
            for (int nt = 0; nt < 4; nt++) {
                ldsm_x2(bh[nt], base + BOFS + (uint32_t)(wn + nt * 8) * 80 + b_off + ko);
                if (TERMS == 3)
                    ldsm_x2(bl[nt], base + 3 * TILE_B + (uint32_t)(wn + nt * 8) * 80 + b_off + ko);
            }
#pragma unroll
            for (int mt = 0; mt < 4; mt++) {
                uint32_t ah[4], al[4];
                ldsm_x4(ah, base + (uint32_t)(wm + mt * 16) * 80 + a_off + ko);
                if (TERMS == 3)
                    ldsm_x4(al, base + TILE_B + (uint32_t)(wm + mt * 16) * 80 + a_off + ko);
#pragma unroll
                for (int nt = 0; nt < 4; nt++) {
                    mma_bf16(acc[mt][nt], ah, bh[nt]);
                    if (TERMS == 3) {
                        mma_bf16(acc[mt][nt], ah, bl[nt]);
                        mma_bf16(acc[mt][nt], al, bh[nt]);
                    }
                }
            }
        }
        __syncthreads();   // protect buffer c&1 from chunk c+2's cp.async next iter
    }

#pragma unroll
    for (int mt = 0; mt < 4; mt++) {
        const int row0 = bm + wm + mt * 16 + (lane >> 2);
#pragma unroll
        for (int nt = 0; nt < 4; nt++) {
            const int col = bn + wn + nt * 8 + (lane & 3) * 2;
#pragma unroll
            for (int half = 0; half < 2; half++) {
                const int row = row0 + half * 8;
                float vx = acc[mt][nt][half * 2] * alpha;
                float vy = acc[mt][nt][half * 2 + 1] * alpha;
                if (Oh) {
                    uint32_t hp, lp;
                    split2(vx, vy, hp, lp);
                    *(uint32_t*)(Oh + (size_t)row * N + col) = hp;
                    *(uint32_t*)(Ol + (size_t)row * N + col) = lp;
                } else {
                    if (bias) { vx += bias[col]; vy += bias[col + 1]; }
                    if (resid) {
                        float2 t = *(const float2*)(resid + (size_t)row * N + col);
                        vx += t.x; vy += t.y;
                    }
                    *(float2*)(C + (size_t)row * N + col) = make_float2(vx, vy);
                }
            }
        }
    }
}

// ================================================================
// FUSED scores + softmax + P·V  (R11-validated, 256 threads)
// ================================================================
#define FS_QSP  4608
#define FS_QT   (2 * FS_QSP)
#define FS_KSP  18432
#define FS_KT   (2 * FS_KSP)
#define FS_SROW 4128
#define FS_SMEM (FS_QT + 2 * FS_KT + 32 * FS_SROW)   // 215040

__global__ void __launch_bounds__(256, 1) fused_attn()
{
    extern __shared__ char sm[];
    const int tid = threadIdx.x;
    const int lane = tid & 31;
    const int wid = tid >> 5;
    const int z = blockIdx.y;
    const int b = z >> 4;
    const int h = z & 15;
    const int q0 = b * NC_ + blockIdx.x * 32;
    const int kb = b * NS_;

    char* smQ = sm;
    char* smK = sm + FS_QT;
    char* smS = sm + FS_QT + 2 * FS_KT;
    const uint32_t uQ = smem_u32(smQ);
    const uint32_t uK = smem_u32(smK);
    const uint32_t uS = smem_u32(smS);

    // ---- Phase 1: scores ----
#pragma unroll
    for (int it = 0; it < 2; it++) {
        const int idx = (it << 8) + tid;
        const int sp = idx >> 8;
        const int r = (idx >> 3) & 31;
        const int s = idx & 7;
        const __nv_bfloat16* src = sp ? g_ql : g_qh;
        uint4 v = *(const uint4*)(src + (size_t)(q0 + r) * INNER_ + h * 64 + s * 8);
        *(uint4*)(smQ + sp * FS_QSP + r * 144 + s * 16) = v;
    }
#pragma unroll
    for (int it = 0; it < 8; it++) {
        const int idx = (it << 8) + tid;
        const int sp = idx >> 10;
        const int r = (idx >> 3) & 127;
        const int s = idx & 7;
        const __nv_bfloat16* src = sp ? g_kl : g_kh;
        uint4 v = *(const uint4*)(src + (size_t)(kb + r) * INNER_ + h * 64 + s * 8);
        *(uint4*)(smK + sp * FS_KSP + r * 144 + s * 16) = v;
    }
    __syncthreads();

    const int wm = (wid >> 2) * 16;
    const int wn = (wid & 3) * 32;
    const uint32_t a_off = (uint32_t)(lane & 15) * 144 + (uint32_t)(lane >> 4) * 16;
    const uint32_t b_off = (uint32_t)(lane & 7) * 144 + (uint32_t)((lane >> 3) & 1) * 16;

    for (int kc = 0; kc < 8; kc++) {
        uint4 g[8];
        if (kc + 1 < 8) {
            const int krow = kb + (kc + 1) * 128;
#pragma unroll
            for (int it = 0; it < 8; it++) {
                const int idx = (it << 8) + tid;
                const int sp = idx >> 10;
                const int r = (idx >> 3) & 127;
                const int s = idx & 7;
                const __nv_bfloat16* src = sp ? g_kl : g_kh;
                g[it] = *(const uint4*)(src + (size_t)(krow + r) * INNER_ + h * 64 + s * 8);
            }
        }
        float acc[4][4];
#pragma unroll
        for (int nt = 0; nt < 4; nt++)
#pragma unroll
            for (int r = 0; r < 4; r++) acc[nt][r] = 0.f;

        const uint32_t kbuf = uK + (uint32_t)(kc & 1) * FS_KT;
#pragma unroll
        for (int kk = 0; kk < 4; kk++) {
            const uint32_t ko = kk * 32;
            uint32_t ah[4], al[4];
            ldsm_x4(ah, uQ + (uint32_t)wm * 144 + a_off + ko);
            ldsm_x4(al, uQ + FS_QSP + (uint32_t)wm * 144 + a_off + ko);
            uint32_t bh[4][2], bl[4][2];
#pragma unroll
            for (int nt = 0; nt < 4; nt++) {
                ldsm_x2(bh[nt], kbuf + (uint32_t)(wn + nt * 8) * 144 + b_off + ko);
                ldsm_x2(bl[nt], kbuf + FS_KSP + (uint32_t)(wn + nt * 8) * 144 + b_off + ko);
            }
#pragma unroll
            for (int nt = 0; nt < 4; nt++) {
                mma_bf16(acc[nt], ah, bh[nt]);
                mma_bf16(acc[nt], ah, bl[nt]);
                mma_bf16(acc[nt], al, bh[nt]);
            }
        }
#pragma unroll
        for (int nt = 0; nt < 4; nt++) {
            const int col = kc * 128 + wn + nt * 8 + (lane & 3) * 2;
#pragma unroll
            for (int half = 0; half < 2; half++) {
                const int row = wm + (lane >> 2) + half * 8;
                *(float2*)(smS + row * FS_SROW + col * 4) =
                    make_float2(acc[nt][half * 2], acc[nt][half * 2 + 1]);
            }
        }
        if (kc + 1 < 8) {
            char* dst = smK + ((kc + 1) & 1) * FS_KT;
#pragma unroll
            for (int it = 0; it < 8; it++) {
                const int idx = (it << 8) + tid;
                const int sp = idx >> 10;
                const int r = (idx >> 3) & 127;
                const int s = idx & 7;
                *(uint4*)(dst + sp * FS_KSP + r * 144 + s * 16) = g[it];
            }
        }
        __syncthreads();
    }

    // ---- Phase 2: softmax; probs fp16 to own smem rows + global ----
    char* gz = (char*)g_attn + (((size_t)z << 12) + (size_t)blockIdx.x * 32) * 2048;
#pragma unroll
    for (int rr = 0; rr < 4; rr++) {
        const int r = wid * 4 + rr;
        char* rb = smS + r * FS_SROW;
        float4 v[8];
#pragma unroll
        for (int it = 0; it < 8; it++) v[it] = *(const float4*)(rb + lane * 16 + it * 512);

        float m = -1e30f;
#pragma unroll
        for (int it = 0; it < 8; it++)
            m = fmaxf(m, fmaxf(fmaxf(v[it].x, v[it].y), fmaxf(v[it].z, v[it].w)));
#pragma unroll
        for (int o = 16; o; o >>= 1) m = fmaxf(m, __shfl_xor_sync(0xffffffffu, m, o));

        float s = 0.f;
#pragma unroll
        for (int it = 0; it < 8; it++) {
            v[it].x = __expf(v[it].x - m); v[it].y = __expf(v[it].y - m);
            v[it].z = __expf(v[it].z - m); v[it].w = __expf(v[it].w - m);
            s += (v[it].x + v[it].y) + (v[it].z + v[it].w);
        }
#pragma unroll
        for (int o = 16; o; o >>= 1) s += __shfl_xor_sync(0xffffffffu, s, o);
        const float inv = 1.f / s;

        char* grow = gz + (size_t)r * 2048;
#pragma unroll
        for (int it = 0; it < 8; it++) {
            uint2 p = make_uint2(packh2(v[it].x * inv, v[it].y * inv),
                                 packh2(v[it].z * inv, v[it].w * inv));
            const int cofs = (it * 128 + lane * 4) * 2;
            *(uint2*)(rb + cofs) = p;
            *(uint2*)(grow + cofs) = p;
        }
    }
    __syncthreads();

    // ---- Phase 3: O = P @ V^T  (64-k chunks) ----
    const __half* vth = g_vth + (size_t)z * 64 * NS_;
    const int wd = (wid & 3) * 16;
    const uint32_t ap_off = (uint32_t)(lane & 15) * FS_SROW + (uint32_t)(lane >> 4) * 16;

    float acco[2][4];
#pragma unroll
    for (int nt = 0; nt < 2; nt++)
#pragma unroll
        for (int r = 0; r < 4; r++) acco[nt][r] = 0.f;

#define FV_LOAD(c_, gArr_)                                                            \
    {                                                                                 \
        _Pragma("unroll")                                                             \
        for (int it = 0; it < 2; it++) {                                              \
            const int idx = (it << 8) + tid;                                          \
            const int r = idx >> 3;                                                   \
            const int s = idx & 7;                                                    \
            gArr_[it] = *(const uint4*)(vth + (size_t)r * NS_ + (c_) * 64 + s * 8);   \
        }                                                                             \
    }
#define FV_STORE(buf_, gArr_)                                                         \
    {                                                                                 \
        char* dst = smK + (buf_) * FS_KT;                                             \
        _Pragma("unroll")                                                             \
        for (int it = 0; it < 2; it++) {                                              \
            const int idx = (it << 8) + tid;                                          \
            const int r = idx >> 3;                                                   \
            const int s = idx & 7;                                                    \
            *(uint4*)(dst + r * 144 + s * 16) = gArr_[it];                            \
        }                                                                             \
    }

    {
        uint4 g[2];
        FV_LOAD(0, g);
        FV_STORE(0, g);
    }
    __syncthreads();

    for (int c = 0; c < 16; c++) {
        uint4 g[2];
        if (c + 1 < 16) FV_LOAD(c + 1, g);
        {
            const uint32_t vbuf = uK + (uint32_t)(c & 1) * FS_KT;
#pragma unroll
            for (int kk = 0; kk < 4; kk++) {
                const uint32_t ko = kk * 32;
                uint32_t ah[4];
                ldsm_x4(ah, uS + (uint32_t)wm * FS_SROW + ap_off + (uint32_t)c * 128 + ko);
                uint32_t bh[2][2];
#pragma unroll
                for (int nt = 0; nt < 2; nt++)
                    ldsm_x2(bh[nt], vbuf + (uint32_t)(wd + nt * 8) * 144 + b_off + ko);
#pragma unroll
                for (int nt = 0; nt < 2; nt++)
                    mma_f16(acco[nt], ah, bh[nt]);
            }
        }
        if (c + 1 < 16) FV_STORE((c + 1) & 1, g);
        __syncthreads();
    }

#pragma unroll
    for (int nt = 0; nt < 2; nt++) {
        const int col = h * 64 + wd + nt * 8 + (lane & 3) * 2;
#pragma unroll
        for (int half = 0; half < 2; half++) {
            const int row = q0 + wm + (lane >> 2) + half * 8;
            *(uint32_t*)(g_avh + (size_t)row * INNER_ + col) =
                pack2(acco[nt][half * 2], acco[nt][half * 2 + 1]);
        }
    }
}

// ================================================================
// attn_mean from fp16 probs (2048 B rows)
// ================================================================
__global__ void attn_mean_kernel(float* __restrict__ out2)
{
    const size_t idx = (size_t)blockIdx.x * 256 + threadIdx.x;
    const size_t e0 = idx << 2;
    const int b = (int)(e0 >> 22);
    const int q = (int)((e0 >> 10) & 4095);
    const int k = (int)(e0 & 1023);
    const __half* pb = (const __half*)g_attn;

    float s0 = 0.f, s1 = 0.f, s2 = 0.f, s3 = 0.f;
#pragma unroll
    for (int h = 0; h < H_; h++) {
        const size_t row = ((size_t)(b * H_ + h) << 12) + q;
        uint2 hv = *(const uint2*)(pb + row * 1024 + k);
        float2 h0 = __half22float2(*(__half2*)&hv.x);
        float2 h1 = __half22float2(*(__half2*)&hv.y);
        s0 += h0.x; s1 += h0.y; s2 += h1.x; s3 += h1.y;
    }
    const float c = 1.0f / 16.0f;
    *(float4*)(out2 + e0) = make_float4(s0 * c, s1 * c, s2 * c, s3 * c);
}

// ================================================================
// fp32 -> bf16 hi/lo split
// ================================================================
__global__ void split_kernel(const float4* __restrict__ in,
                             uint2* __restrict__ oh, uint2* __restrict__ ol, int n4)
{
    const int i = blockIdx.x * 256 + threadIdx.x;
    if (i >= n4) return;
    float4 v = in[i];
    __align__(8) __nv_bfloat16 h[4], l[4];
    const float f[4] = {v.x, v.y, v.z, v.w};
#pragma unroll
    for (int j = 0; j < 4; j++) {
        h[j] = __float2bfloat16(f[j]);
        l[j] = __float2bfloat16(f[j] - __bfloat162float(h[j]));
    }
    oh[i] = *(uint2*)h;
    ol[i] = *(uint2*)l;
}

// ================================================================
// Transpose + split weights: fp32 [R][Ncol] -> bf16 [Ncol][R] hi/lo
// ================================================================
__global__ void tsplit_kernel(const float* __restrict__ in,
                              __nv_bfloat16* __restrict__ oh,
                              __nv_bfloat16* __restrict__ ol, int R, int Ncol)
{
    __shared__ float t[32][33];
    const int bx = blockIdx.x * 32, by = blockIdx.y * 32;
    const int tx = threadIdx.x, ty = threadIdx.y;
#pragma unroll
    for (int i = 0; i < 32; i += 8)
        t[ty + i][tx] = in[(size_t)(by + ty + i) * Ncol + bx + tx];
    __syncthreads();
#pragma unroll
    for (int i = 0; i < 32; i += 8) {
        const float v = t[tx][ty + i];
        const size_t o = (size_t)(bx + ty + i) * R + by + tx;
        __nv_bfloat16 h = __float2bfloat16(v);
        oh[o] = h;
        ol[o] = __float2bfloat16(v - __bfloat162float(h));
    }
}

// ================================================================
// V^T to fp16
// ================================================================
__global__ void vtsplit_kernel()
{
    __shared__ float t[32][33];
    const int b = blockIdx.z;
    const int bx = blockIdx.x * 32;
    const int by = blockIdx.y * 32;
    const int tx = threadIdx.x, ty = threadIdx.y;
    const float* in = g_v + (size_t)b * NS_ * INNER_;
#pragma unroll
    for (int i = 0; i < 32; i += 8)
        t[ty + i][tx] = in[(size_t)(by + ty + i) * INNER_ + bx + tx];
    __syncthreads();
#pragma unroll
    for (int i = 0; i < 32; i += 8) {
        const float v = t[tx][ty + i];
        g_vth[(size_t)(b * 1024 + bx + ty + i) * NS_ + by + tx] = __float2half_rn(v);
    }
}

// ================================================================
// LayerNorm
// ================================================================
__global__ void ln_kernel(const float* __restrict__ gamma,
                          const float* __restrict__ beta,
                          float* __restrict__ out)
{
    __shared__ float reds[9];
    __shared__ float redq[9];
    const size_t row = blockIdx.x;
    const int tid = threadIdx.x;

    float4 x = reinterpret_cast<const float4*>(g_x + row * CD_)[tid];
    float s = x.x + x.y + x.z + x.w;
    float q = x.x * x.x + x.y * x.y + x.z * x.z + x.w * x.w;
#pragma unroll
    for (int o = 16; o; o >>= 1) {
        s += __shfl_xor_sync(0xffffffffu, s, o);
        q += __shfl_xor_sync(0xffffffffu, q, o);
    }
    if ((tid & 31) == 0) { reds[tid >> 5] = s; redq[tid >> 5] = q; }
    __syncthreads();
    if (tid == 0) {
        float ss = 0.f, qq = 0.f;
#pragma unroll
        for (int i = 0; i < 8; i++) { ss += reds[i]; qq += redq[i]; }
        reds[8] = ss; redq[8] = qq;
    }
    __syncthreads();
    const float mu = reds[8] * (1.0f / 1024.0f);
    const float var = redq[8] * (1.0f / 1024.0f) - mu * mu;
    const float rstd = rsqrtf(var + LN_EPS);

    float4 g = reinterpret_cast<const float4*>(gamma)[tid];
    float4 bb = reinterpret_cast<const float4*>(beta)[tid];
    float4 r;
    r.x = (x.x - mu) * rstd * g.x + bb.x;
    r.y = (x.y - mu) * rstd * g.y + bb.y;
    r.z = (x.z - mu) * rstd * g.z + bb.z;
    r.w = (x.w - mu) * rstd * g.w + bb.w;
    reinterpret_cast<float4*>(out + row * CD_)[tid] = r;
}

// ================================================================
extern "C" void kernel_launch(void* const* d_in, const int* in_sizes, int n_in,
                              void* d_out, int out_size)
{
    const float* content = (const float*)d_in[0];
    const float* style   = (const float*)d_in[1];
    const float* Wq      = (const float*)d_in[2];
    const float* Wk      = (const float*)d_in[3];
    const float* Wv      = (const float*)d_in[4];
    const float* Wo      = (const float*)d_in[5];
    const float* bo      = (const float*)d_in[6];
    const float* gamma   = (const float*)d_in[7];
    const float* beta    = (const float*)d_in[8];
    float* out = (float*)d_out;
    float* out_attn = out + (size_t)B_ * NC_ * CD_;

    cudaFuncSetAttribute(gemm_mma<3>, cudaFuncAttributeMaxDynamicSharedMemorySize, GSMEM3_B);
    cudaFuncSetAttribute(gemm_mma<1>, cudaFuncAttributeMaxDynamicSharedMemorySize, GSMEM1_B);
    cudaFuncSetAttribute(fused_attn, cudaFuncAttributeMaxDynamicSharedMemorySize, FS_SMEM);

    float *p_x, *p_v;
    __nv_bfloat16 *p_chi, *p_clo, *p_shi, *p_slo, *p_avh;
    __nv_bfloat16 *p_qh, *p_ql, *p_kh, *p_kl;
    __nv_bfloat16 *p_wqh, *p_wql, *p_wkh, *p_wkl, *p_wvh, *p_wvl, *p_woh;
    cudaGetSymbolAddress((void**)&p_v,   g_v);
    cudaGetSymbolAddress((void**)&p_x,   g_x);
    cudaGetSymbolAddress((void**)&p_chi, g_c_hi);
    cudaGetSymbolAddress((void**)&p_clo, g_c_lo);
    cudaGetSymbolAddress((void**)&p_shi, g_s_hi);
    cudaGetSymbolAddress((void**)&p_slo, g_s_lo);
    cudaGetSymbolAddress((void**)&p_qh,  g_qh);
    cudaGetSymbolAddress((void**)&p_ql,  g_ql);
    cudaGetSymbolAddress((void**)&p_kh,  g_kh);
    cudaGetSymbolAddress((void**)&p_kl,  g_kl);
    cudaGetSymbolAddress((void**)&p_avh, g_avh);
    cudaGetSymbolAddress((void**)&p_wqh, g_wqt_hi);
    cudaGetSymbolAddress((void**)&p_wql, g_wqt_lo);
    cudaGetSymbolAddress((void**)&p_wkh, g_wkt_hi);
    cudaGetSymbolAddress((void**)&p_wkl, g_wkt_lo);
    cudaGetSymbolAddress((void**)&p_wvh, g_wvt_hi);
    cudaGetSymbolAddress((void**)&p_wvl, g_wvt_lo);
    cudaGetSymbolAddress((void**)&p_woh, g_wot_hi);

    // 0) splits
    split_kernel<<<(B_ * NC_ * CD_ / 4 + 255) / 256, 256>>>(
        (const float4*)content, (uint2*)p_chi, (uint2*)p_clo, B_ * NC_ * CD_ / 4);
    split_kernel<<<(B_ * NS_ * SD_ / 4 + 255) / 256, 256>>>(
        (const float4*)style, (uint2*)p_shi, (uint2*)p_slo, B_ * NS_ * SD_ / 4);
    tsplit_kernel<<<dim3(32, 32), dim3(32, 8)>>>(Wq, p_wqh, p_wql, CD_, INNER_);
    tsplit_kernel<<<dim3(32, 24), dim3(32, 8)>>>(Wk, p_wkh, p_wkl, SD_, INNER_);
    tsplit_kernel<<<dim3(32, 24), dim3(32, 8)>>>(Wv, p_wvh, p_wvl, SD_, INNER_);
    // Wo: only hi needed (1-term O-proj). lo lands in g_ql, overwritten by Q proj after.
    tsplit_kernel<<<dim3(32, 32), dim3(32, 8)>>>(Wo, p_woh, p_ql /*discard*/, INNER_, CD_);

    // 1) Q proj -> bf16 hi/lo (pre-scaled 1/8)
    gemm_mma<3><<<dim3(INNER_ / 128, B_ * NC_ / 128), 256, GSMEM3_B>>>(
        p_chi, p_clo, p_wqh, p_wql, nullptr, p_qh, p_ql,
        B_ * NC_, INNER_, CD_, nullptr, nullptr, 0.125f);
    // 2) K proj -> bf16 hi/lo
    gemm_mma<3><<<dim3(INNER_ / 128, B_ * NS_ / 128), 256, GSMEM3_B>>>(
        p_shi, p_slo, p_wkh, p_wkl, nullptr, p_kh, p_kl,
        B_ * NS_, INNER_, SD_, nullptr, nullptr, 1.0f);
    // 3) V proj -> fp32, then per-head transpose to fp16
    gemm_mma<3><<<dim3(INNER_ / 128, B_ * NS_ / 128), 256, GSMEM3_B>>>(
        p_shi, p_slo, p_wvh, p_wvl, p_v, nullptr, nullptr,
        B_ * NS_, INNER_, SD_, nullptr, nullptr, 1.0f);
    vtsplit_kernel<<<dim3(32, 32, B_), dim3(32, 8)>>>();

    // 4) FUSED scores + softmax + P·V (256 threads, R11 config)
    fused_attn<<<dim3(NC_ / 32, B_ * H_), 256, FS_SMEM>>>();
    // 5) head-mean -> second output
    attn_mean_kernel<<<B_ * NC_ * NS_ / 4 / 256, 256>>>(out_attn);
    // 6) O proj (1-term) + bias + residual
    gemm_mma<1><<<dim3(CD_ / 128, B_ * NC_ / 128), 256, GSMEM1_B>>>(
        p_avh, nullptr, p_woh, nullptr, p_x, nullptr, nullptr,
        B_ * NC_, CD_, INNER_, bo, content, 1.0f);
    // 7) LayerNorm -> first output
    ln_kernel<<<B_ * NC_, 256>>>(gamma, beta, out);
}

// round 15
// speedup vs baseline: 1.1375x; 1.0642x over previous
#include <cuda_runtime.h>
#include <cuda_bf16.h>
#include <cuda_fp16.h>
#include <math.h>
#include <stdint.h>

#define B_    4
#define NC_   4096
#define NS_   1024
#define CD_   1024
#define SD_   768
#define H_    16
#define D_    64
#define INNER_ 1024
#define LN_EPS 1e-5f

// ---------------- static device scratch ----------------
__device__ float g_attn[(size_t)B_ * H_ * NC_ * NS_];   // probs fp16 rows (2048 B/row used)
__device__ float g_x[(size_t)B_ * NC_ * CD_];
__device__ float g_v[(size_t)B_ * NS_ * INNER_];

__device__ __nv_bfloat16 g_c_hi[(size_t)B_ * NC_ * CD_];
__device__ __nv_bfloat16 g_c_lo[(size_t)B_ * NC_ * CD_];
__device__ __nv_bfloat16 g_s_hi[(size_t)B_ * NS_ * SD_];
__device__ __nv_bfloat16 g_s_lo[(size_t)B_ * NS_ * SD_];
__device__ __nv_bfloat16 g_qh[(size_t)B_ * NC_ * INNER_];   // Q (pre-scaled 1/8) hi/lo
__device__ __nv_bfloat16 g_ql[(size_t)B_ * NC_ * INNER_];
__device__ __nv_bfloat16 g_kh[(size_t)B_ * NS_ * INNER_];
__device__ __nv_bfloat16 g_kl[(size_t)B_ * NS_ * INNER_];
__device__ __half        g_vth[(size_t)B_ * INNER_ * NS_];  // V^T per head [z*64+d][s], fp16
__device__ __nv_bfloat16 g_avh[(size_t)B_ * NC_ * INNER_];  // attended, bf16

__device__ __nv_bfloat16 g_wqt_hi[INNER_ * CD_];
__device__ __nv_bfloat16 g_wqt_lo[INNER_ * CD_];
__device__ __nv_bfloat16 g_wkt_hi[INNER_ * SD_];
__device__ __nv_bfloat16 g_wkt_lo[INNER_ * SD_];
__device__ __nv_bfloat16 g_wvt_hi[INNER_ * SD_];
__device__ __nv_bfloat16 g_wvt_lo[INNER_ * SD_];
__device__ __nv_bfloat16 g_wot_hi[CD_ * INNER_];

// ================= helpers =================
__device__ __forceinline__ uint32_t smem_u32(const void* p) {
    uint32_t a;
    asm("{ .reg .u64 t; cvta.to.shared.u64 t, %1; cvt.u32.u64 %0, t; }" : "=r"(a) : "l"(p));
    return a;
}
__device__ __forceinline__ void ldsm_x4(uint32_t* f, uint32_t addr) {
    asm volatile("ldmatrix.sync.aligned.m8n8.x4.shared.b16 {%0,%1,%2,%3}, [%4];"
                 : "=r"(f[0]), "=r"(f[1]), "=r"(f[2]), "=r"(f[3]) : "r"(addr));
}
__device__ __forceinline__ void ldsm_x2(uint32_t* f, uint32_t addr) {
    asm volatile("ldmatrix.sync.aligned.m8n8.x2.shared.b16 {%0,%1}, [%2];"
                 : "=r"(f[0]), "=r"(f[1]) : "r"(addr));
}
__device__ __forceinline__ void mma_bf16(float* c, const uint32_t* a, const uint32_t* b) {
    asm volatile("mma.sync.aligned.m16n8k16.row.col.f32.bf16.bf16.f32 "
                 "{%0,%1,%2,%3}, {%4,%5,%6,%7}, {%8,%9}, {%0,%1,%2,%3};"
                 : "+f"(c[0]), "+f"(c[1]), "+f"(c[2]), "+f"(c[3])
                 : "r"(a[0]), "r"(a[1]), "r"(a[2]), "r"(a[3]), "r"(b[0]), "r"(b[1]));
}
__device__ __forceinline__ void mma_f16(float* c, const uint32_t* a, const uint32_t* b) {
    asm volatile("mma.sync.aligned.m16n8k16.row.col.f32.f16.f16.f32 "
                 "{%0,%1,%2,%3}, {%4,%5,%6,%7}, {%8,%9}, {%0,%1,%2,%3};"
                 : "+f"(c[0]), "+f"(c[1]), "+f"(c[2]), "+f"(c[3])
                 : "r"(a[0]), "r"(a[1]), "r"(a[2]), "r"(a[3]), "r"(b[0]), "r"(b[1]));
}
__device__ __forceinline__ void split2(float x, float y, uint32_t& hp, uint32_t& lp) {
    __nv_bfloat16 hx = __float2bfloat16(x), hy = __float2bfloat16(y);
    hp = ((uint32_t)*(uint16_t*)&hy << 16) | *(uint16_t*)&hx;
    __nv_bfloat16 lx = __float2bfloat16(x - __bfloat162float(hx));
    __nv_bfloat16 ly = __float2bfloat16(y - __bfloat162float(hy));
    lp = ((uint32_t)*(uint16_t*)&ly << 16) | *(uint16_t*)&lx;
}
__device__ __forceinline__ uint32_t pack2(float x, float y) {
    __nv_bfloat16 hx = __float2bfloat16(x), hy = __float2bfloat16(y);
    return ((uint32_t)*(uint16_t*)&hy << 16) | *(uint16_t*)&hx;
}
__device__ __forceinline__ uint32_t packh2(float x, float y) {
    __half2 t = __floats2half2_rn(x, y);
    return *(uint32_t*)&t;
}

#define CP16(dst, src)  asm volatile("cp.async.cg.shared.global [%0], [%1], 16;" :: "r"(dst), "l"(src))
#define CP_COMMIT()     asm volatile("cp.async.commit_group;" ::: "memory")
#define CP_WAIT0()      asm volatile("cp.async.wait_group 0;" ::: "memory")
#define CP_WAIT1()      asm volatile("cp.async.wait_group 1;" ::: "memory")

// ================================================================
// Templated bf16-split GEMM with cp.async staging (R13-validated).
// ================================================================
#define TILE_B    10240
#define GSMEM3_B  (2 * 4 * TILE_B)   // 81920
#define GSMEM1_B  (2 * 2 * TILE_B)   // 40960

template <int TERMS>
__global__ void __launch_bounds__(256, 2) gemm_mma(
    const __nv_bfloat16* __restrict__ Ah, const __nv_bfloat16* __restrict__ Al,
    const __nv_bfloat16* __restrict__ Bh, const __nv_bfloat16* __restrict__ Bl,
    float* __restrict__ C, __nv_bfloat16* __restrict__ Oh, __nv_bfloat16* __restrict__ Ol,
    int M, int N, int K,
    const float* __restrict__ bias, const float* __restrict__ resid, float alpha)
{
    extern __shared__ char sm[];
    const int tid = threadIdx.x;
    const int lane = tid & 31;
    const int wid = tid >> 5;
    const int bm = blockIdx.y * 128;
    const int bn = blockIdx.x * 128;
    const int nch = K >> 5;
    const int NIT = (TERMS == 3) ? 8 : 4;
    const int NTILES = (TERMS == 3) ? 4 : 2;
    const int BUFT = NTILES * TILE_B;
    const int BOFS = (TERMS == 3) ? 2 * TILE_B : TILE_B;

    const int wm = (wid >> 2) * 64;
    const int wn = (wid & 3) * 32;

    const uint32_t sA = smem_u32(sm);
    const uint32_t a_off = (uint32_t)(lane & 15) * 80 + (uint32_t)(lane >> 4) * 16;
    const uint32_t b_off = (uint32_t)(lane & 7) * 80 + (uint32_t)((lane >> 3) & 1) * 16;

    float acc[4][4][4];
#pragma unroll
    for (int mt = 0; mt < 4; mt++)
#pragma unroll
        for (int nt = 0; nt < 4; nt++)
#pragma unroll
            for (int r = 0; r < 4; r++) acc[mt][nt][r] = 0.f;

    auto issue = [&](int c, int buf) {
        const int ko = c << 5;
#pragma unroll
        for (int it = 0; it < NIT; it++) {
            const int idx = (it << 8) + tid;
            int t, slot;
            if (TERMS == 3) { t = idx >> 9; slot = t; }
            else            { slot = idx >> 9; t = slot * 2; }
            const int r = (idx >> 2) & 127;
            const int s = idx & 3;
            const __nv_bfloat16* src = (t == 0) ? Ah : (t == 1) ? Al : (t == 2) ? Bh : Bl;
            const int rb = (t < 2) ? bm : bn;
            CP16(sA + buf * BUFT + slot * TILE_B + r * 80 + s * 16,
                 src + (size_t)(rb + r) * K + ko + s * 8);
        }
        CP_COMMIT();
    };

    issue(0, 0);

    for (int c = 0; c < nch; c++) {
        if (c + 1 < nch) { issue(c + 1, (c + 1) & 1); CP_WAIT1(); }
        else             { CP_WAIT0(); }
        __syncthreads();

        const uint32_t base = sA + (uint32_t)(c & 1) * BUFT;
#pragma unroll
        for (int kk = 0; kk < 2; kk++) {
            const uint32_t ko = kk * 32;
            uint32_t bh[4][2], bl[4][2];
#pragma unroll
            for (int nt = 0; nt < 4; nt++) {
                ldsm_x2(bh[nt], base + BOFS + (uint32_t)(wn + nt * 8) * 80 + b_off + ko);
                if (TERMS == 3)
                    ldsm_x2(bl[nt], base + 3 * TILE_B + (uint32_t)(wn + nt * 8) * 80 + b_off + ko);
            }
#pragma unroll
            for (int mt = 0; mt < 4; mt++) {
                uint32_t ah[4], al[4];
                ldsm_x4(ah, base + (uint32_t)(wm + mt * 16) * 80 + a_off + ko);
                if (TERMS == 3)
                    ldsm_x4(al, base + TILE_B + (uint32_t)(wm + mt * 16) * 80 + a_off + ko);
#pragma unroll
                for (int nt = 0; nt < 4; nt++) {
                    mma_bf16(acc[mt][nt], ah, bh[nt]);
                    if (TERMS == 3) {
                        mma_bf16(acc[mt][nt], ah, bl[nt]);
                        mma_bf16(acc[mt][nt], al, bh[nt]);
                    }
                }
            }
        }
        __syncthreads();
    }

#pragma unroll
    for (int mt = 0; mt < 4; mt++) {
        const int row0 = bm + wm + mt * 16 + (lane >> 2);
#pragma unroll
        for (int nt = 0; nt < 4; nt++) {
            const int col = bn + wn + nt * 8 + (lane & 3) * 2;
#pragma unroll
            for (int half = 0; half < 2; half++) {
                const int row = row0 + half * 8;
                float vx = acc[mt][nt][half * 2] * alpha;
                float vy = acc[mt][nt][half * 2 + 1] * alpha;
                if (Oh) {
                    uint32_t hp, lp;
                    split2(vx, vy, hp, lp);
                    *(uint32_t*)(Oh + (size_t)row * N + col) = hp;
                    *(uint32_t*)(Ol + (size_t)row * N + col) = lp;
                } else {
                    if (bias) { vx += bias[col]; vy += bias[col + 1]; }
                    if (resid) {
                        float2 t = *(const float2*)(resid + (size_t)row * N + col);
                        vx += t.x; vy += t.y;
                    }
                    *(float2*)(C + (size_t)row * N + col) = make_float2(vx, vy);
                }
            }
        }
    }
}

// ================================================================
// FUSED scores + softmax + P·V.
// Phase-1 K streaming via cp.async; Phase-3 two 512-col V chunks
// (64 rows x 1040 B stride) in the dead K region.
// ================================================================
#define FS_QSP  4608
#define FS_QT   (2 * FS_QSP)
#define FS_KSP  18432
#define FS_KT   (2 * FS_KSP)
#define FS_SROW 4128
#define FS_SMEM (FS_QT + 2 * FS_KT + 32 * FS_SROW)   // 215040

__global__ void __launch_bounds__(256, 1) fused_attn()
{
    extern __shared__ char sm[];
    const int tid = threadIdx.x;
    const int lane = tid & 31;
    const int wid = tid >> 5;
    const int z = blockIdx.y;
    const int b = z >> 4;
    const int h = z & 15;
    const int q0 = b * NC_ + blockIdx.x * 32;
    const int kb = b * NS_;

    char* smQ = sm;
    char* smK = sm + FS_QT;
    char* smS = sm + FS_QT + 2 * FS_KT;
    const uint32_t uQ = smem_u32(smQ);
    const uint32_t uK = smem_u32(smK);
    const uint32_t uS = smem_u32(smS);

    auto issueK = [&](int c, int buf) {
        const int krow = kb + c * 128;
#pragma unroll
        for (int it = 0; it < 8; it++) {
            const int idx = (it << 8) + tid;
            const int sp = idx >> 10;
            const int r = (idx >> 3) & 127;
            const int s = idx & 7;
            const __nv_bfloat16* src = sp ? g_kl : g_kh;
            CP16(uK + buf * FS_KT + sp * FS_KSP + r * 144 + s * 16,
                 src + (size_t)(krow + r) * INNER_ + h * 64 + s * 8);
        }
        CP_COMMIT();
    };

    issueK(0, 0);

    // Q tile (synchronous, tiny)
#pragma unroll
    for (int it = 0; it < 2; it++) {
        const int idx = (it << 8) + tid;
        const int sp = idx >> 8;
        const int r = (idx >> 3) & 31;
        const int s = idx & 7;
        const __nv_bfloat16* src = sp ? g_ql : g_qh;
        uint4 v = *(const uint4*)(src + (size_t)(q0 + r) * INNER_ + h * 64 + s * 8);
        *(uint4*)(smQ + sp * FS_QSP + r * 144 + s * 16) = v;
    }

    const int wm = (wid >> 2) * 16;
    const int wn = (wid & 3) * 32;
    const uint32_t a_off = (uint32_t)(lane & 15) * 144 + (uint32_t)(lane >> 4) * 16;
    const uint32_t b_off = (uint32_t)(lane & 7) * 144 + (uint32_t)((lane >> 3) & 1) * 16;

    // ---- Phase 1: scores (cp.async pipelined K) ----
    for (int kc = 0; kc < 8; kc++) {
        if (kc + 1 < 8) { issueK(kc + 1, (kc + 1) & 1); CP_WAIT1(); }
        else            { CP_WAIT0(); }
        __syncthreads();

        float acc[4][4];
#pragma unroll
        for (int nt = 0; nt < 4; nt++)
#pragma unroll
            for (int r = 0; r < 4; r++) acc[nt][r] = 0.f;

        const uint32_t kbuf = uK + (uint32_t)(kc & 1) * FS_KT;
#pragma unroll
        for (int kk = 0; kk < 4; kk++) {
            const uint32_t ko = kk * 32;
            uint32_t ah[4], al[4];
            ldsm_x4(ah, uQ + (uint32_t)wm * 144 + a_off + ko);
            ldsm_x4(al, uQ + FS_QSP + (uint32_t)wm * 144 + a_off + ko);
            uint32_t bh[4][2], bl[4][2];
#pragma unroll
            for (int nt = 0; nt < 4; nt++) {
                ldsm_x2(bh[nt], kbuf + (uint32_t)(wn + nt * 8) * 144 + b_off + ko);
                ldsm_x2(bl[nt], kbuf + FS_KSP + (uint32_t)(wn + nt * 8) * 144 + b_off + ko);
            }
#pragma unroll
            for (int nt = 0; nt < 4; nt++) {
                mma_bf16(acc[nt], ah, bh[nt]);
                mma_bf16(acc[nt], ah, bl[nt]);
                mma_bf16(acc[nt], al, bh[nt]);
            }
        }
#pragma unroll
        for (int nt = 0; nt < 4; nt++) {
            const int col = kc * 128 + wn + nt * 8 + (lane & 3) * 2;
#pragma unroll
            for (int half = 0; half < 2; half++) {
                const int row = wm + (lane >> 2) + half * 8;
                *(float2*)(smS + row * FS_SROW + col * 4) =
                    make_float2(acc[nt][half * 2], acc[nt][half * 2 + 1]);
            }
        }
        __syncthreads();   // protect buffer kc&1 before next issueK overwrites it
    }

    // ---- Phase 2: softmax; probs fp16 to own smem rows + global ----
    char* gz = (char*)g_attn + (((size_t)z << 12) + (size_t)blockIdx.x * 32) * 2048;
#pragma unroll
    for (int rr = 0; rr < 4; rr++) {
        const int r = wid * 4 + rr;
        char* rb = smS + r * FS_SROW;
        float4 v[8];
#pragma unroll
        for (int it = 0; it < 8; it++) v[it] = *(const float4*)(rb + lane * 16 + it * 512);

        float m = -1e30f;
#pragma unroll
        for (int it = 0; it < 8; it++)
            m = fmaxf(m, fmaxf(fmaxf(v[it].x, v[it].y), fmaxf(v[it].z, v[it].w)));
#pragma unroll
        for (int o = 16; o; o >>= 1) m = fmaxf(m, __shfl_xor_sync(0xffffffffu, m, o));

        float s = 0.f;
#pragma unroll
        for (int it = 0; it < 8; it++) {
            v[it].x = __expf(v[it].x - m); v[it].y = __expf(v[it].y - m);
            v[it].z = __expf(v[it].z - m); v[it].w = __expf(v[it].w - m);
            s += (v[it].x + v[it].y) + (v[it].z + v[it].w);
        }
#pragma unroll
        for (int o = 16; o; o >>= 1) s += __shfl_xor_sync(0xffffffffu, s, o);
        const float inv = 1.f / s;

        char* grow = gz + (size_t)r * 2048;
#pragma unroll
        for (int it = 0; it < 8; it++) {
            uint2 p = make_uint2(packh2(v[it].x * inv, v[it].y * inv),
                                 packh2(v[it].z * inv, v[it].w * inv));
            const int cofs = (it * 128 + lane * 4) * 2;
            *(uint2*)(rb + cofs) = p;
            *(uint2*)(grow + cofs) = p;
        }
    }
    __syncthreads();

    // ---- Phase 3: O = P @ V^T, two 512-col V chunks in the dead K region ----
    const __half* vth = g_vth + (size_t)z * 64 * NS_;
    const int wd = (wid & 3) * 16;
    const uint32_t ap_off = (uint32_t)(lane & 15) * FS_SROW + (uint32_t)(lane >> 4) * 16;
    const uint32_t bv_off = (uint32_t)(lane & 7) * 1040 + (uint32_t)((lane >> 3) & 1) * 16;

    float acco[2][4];
#pragma unroll
    for (int nt = 0; nt < 2; nt++)
#pragma unroll
        for (int r = 0; r < 4; r++) acco[nt][r] = 0.f;

#pragma unroll
    for (int c2 = 0; c2 < 2; c2++) {
        // load V chunk: 64 rows x 512 fp16 (1024 B/row) = 4096 uint4 items
#pragma unroll
        for (int it = 0; it < 16; it++) {
            const int item = (it << 8) + tid;
            const int r = item >> 6;           // 0..63
            const int s = item & 63;           // 0..63  (s*16 <= 1008 < 1040)
            *(uint4*)(smK + r * 1040 + s * 16) =
                *(const uint4*)(vth + (size_t)r * NS_ + c2 * 512 + s * 8);
        }
        __syncthreads();

#pragma unroll
        for (int kc2 = 0; kc2 < 8; kc2++) {
#pragma unroll
            for (int kk = 0; kk < 4; kk++) {
                const uint32_t ko = (uint32_t)(kc2 * 128 + kk * 32);
                uint32_t ah[4];
                ldsm_x4(ah, uS + (uint32_t)wm * FS_SROW + ap_off + (uint32_t)c2 * 1024 + ko);
                uint32_t bh[2][2];
#pragma unroll
                for (int nt = 0; nt < 2; nt++)
                    ldsm_x2(bh[nt], uK + (uint32_t)(wd + nt * 8) * 1040 + bv_off + ko);
#pragma unroll
                for (int nt = 0; nt < 2; nt++)
                    mma_f16(acco[nt], ah, bh[nt]);
            }
        }
        if (c2 == 0) __syncthreads();   // before chunk-1 load overwrites smK
    }

    // epilogue: O 32x64 -> g_avh bf16
#pragma unroll
    for (int nt = 0; nt < 2; nt++) {
        const int col = h * 64 + wd + nt * 8 + (lane & 3) * 2;
#pragma unroll
        for (int half = 0; half < 2; half++) {
            const int row = q0 + wm + (lane >> 2) + half * 8;
            *(uint32_t*)(g_avh + (size_t)row * INNER_ + col) =
                pack2(acco[nt][half * 2], acco[nt][half * 2 + 1]);
        }
    }
}

// ================================================================
// attn_mean from fp16 probs (2048 B rows)
// ================================================================
__global__ void attn_mean_kernel(float* __restrict__ out2)
{
    const size_t idx = (size_t)blockIdx.x * 256 + threadIdx.x;
    const size_t e0 = idx << 2;
    const int b = (int)(e0 >> 22);
    const int q = (int)((e0 >> 10) & 4095);
    const int k = (int)(e0 & 1023);
    const __half* pb = (const __half*)g_attn;

    float s0 = 0.f, s1 = 0.f, s2 = 0.f, s3 = 0.f;
#pragma unroll
    for (int h = 0; h < H_; h++) {
        const size_t row = ((size_t)(b * H_ + h) << 12) + q;
        uint2 hv = *(const uint2*)(pb + row * 1024 + k);
        float2 h0 = __half22float2(*(__half2*)&hv.x);
        float2 h1 = __half22float2(*(__half2*)&hv.y);
        s0 += h0.x; s1 += h0.y; s2 += h1.x; s3 += h1.y;
    }
    const float c = 1.0f / 16.0f;
    *(float4*)(out2 + e0) = make_float4(s0 * c, s1 * c, s2 * c, s3 * c);
}

// ================================================================
// fp32 -> bf16 hi/lo split
// ================================================================
__global__ void split_kernel(const float4* __restrict__ in,
                             uint2* __restrict__ oh, uint2* __restrict__ ol, int n4)
{
    const int i = blockIdx.x * 256 + threadIdx.x;
    if (i >= n4) return;
    float4 v = in[i];
    __align__(8) __nv_bfloat16 h[4], l[4];
    const float f[4] = {v.x, v.y, v.z, v.w};
#pragma unroll
    for (int j = 0; j < 4; j++) {
        h[j] = __float2bfloat16(f[j]);
        l[j] = __float2bfloat16(f[j] - __bfloat162float(h[j]));
    }
    oh[i] = *(uint2*)h;
    ol[i] = *(uint2*)l;
}

// ================================================================
// Transpose + split weights: fp32 [R][Ncol] -> bf16 [Ncol][R] hi/lo
// ================================================================
__global__ void tsplit_kernel(const float* __restrict__ in,
                              __nv_bfloat16* __restrict__ oh,
                              __nv_bfloat16* __restrict__ ol, int R, int Ncol)
{
    __shared__ float t[32][33];
    const int bx = blockIdx.x * 32, by = blockIdx.y * 32;
    const int tx = threadIdx.x, ty = threadIdx.y;
#pragma unroll
    for (int i = 0; i < 32; i += 8)
        t[ty + i][tx] = in[(size_t)(by + ty + i) * Ncol + bx + tx];
    __syncthreads();
#pragma unroll
    for (int i = 0; i < 32; i += 8) {
        const float v = t[tx][ty + i];
        const size_t o = (size_t)(bx + ty + i) * R + by + tx;
        __nv_bfloat16 h = __float2bfloat16(v);
        oh[o] = h;
        ol[o] = __float2bfloat16(v - __bfloat162float(h));
    }
}

// ================================================================
// V^T to fp16
// ================================================================
__global__ void vtsplit_kernel()
{
    __shared__ float t[32][33];
    const int b = blockIdx.z;
    const int bx = blockIdx.x * 32;
    const int by = blockIdx.y * 32;
    const int tx = threadIdx.x, ty = threadIdx.y;
    const float* in = g_v + (size_t)b * NS_ * INNER_;
#pragma unroll
    for (int i = 0; i < 32; i += 8)
        t[ty + i][tx] = in[(size_t)(by + ty + i) * INNER_ + bx + tx];
    __syncthreads();
#pragma unroll
    for (int i = 0; i < 32; i += 8) {
        const float v = t[tx][ty + i];
        g_vth[(size_t)(b * 1024 + bx + ty + i) * NS_ + by + tx] = __float2half_rn(v);
    }
}

// ================================================================
// LayerNorm
// ================================================================
__global__ void ln_kernel(const float* __restrict__ gamma,
                          const float* __restrict__ beta,
                          float* __restrict__ out)
{
    __shared__ float reds[9];
    __shared__ float redq[9];
    const size_t row = blockIdx.x;
    const int tid = threadIdx.x;

    float4 x = reinterpret_cast<const float4*>(g_x + row * CD_)[tid];
    float s = x.x + x.y + x.z + x.w;
    float q = x.x * x.x + x.y * x.y + x.z * x.z + x.w * x.w;
#pragma unroll
    for (int o = 16; o; o >>= 1) {
        s += __shfl_xor_sync(0xffffffffu, s, o);
        q += __shfl_xor_sync(0xffffffffu, q, o);
    }
    if ((tid & 31) == 0) { reds[tid >> 5] = s; redq[tid >> 5] = q; }
    __syncthreads();
    if (tid == 0) {
        float ss = 0.f, qq = 0.f;
#pragma unroll
        for (int i = 0; i < 8; i++) { ss += reds[i]; qq += redq[i]; }
        reds[8] = ss; redq[8] = qq;
    }
    __syncthreads();
    const float mu = reds[8] * (1.0f / 1024.0f);
    const float var = redq[8] * (1.0f / 1024.0f) - mu * mu;
    const float rstd = rsqrtf(var + LN_EPS);

    float4 g = reinterpret_cast<const float4*>(gamma)[tid];
    float4 bb = reinterpret_cast<const float4*>(beta)[tid];
    float4 r;
    r.x = (x.x - mu) * rstd * g.x + bb.x;
    r.y = (x.y - mu) * rstd * g.y + bb.y;
    r.z = (x.z - mu) * rstd * g.z + bb.z;
    r.w = (x.w - mu) * rstd * g.w + bb.w;
    reinterpret_cast<float4*>(out + row * CD_)[tid] = r;
}

// ================================================================
extern "C" void kernel_launch(void* const* d_in, const int* in_sizes, int n_in,
                              void* d_out, int out_size)
{
    const float* content = (const float*)d_in[0];
    const float* style   = (const float*)d_in[1];
    const float* Wq      = (const float*)d_in[2];
    const float* Wk      = (const float*)d_in[3];
    const float* Wv      = (const float*)d_in[4];
    const float* Wo      = (const float*)d_in[5];
    const float* bo      = (const float*)d_in[6];
    const float* gamma   = (const float*)d_in[7];
    const float* beta    = (const float*)d_in[8];
    float* out = (float*)d_out;
    float* out_attn = out + (size_t)B_ * NC_ * CD_;

    cudaFuncSetAttribute(gemm_mma<3>, cudaFuncAttributeMaxDynamicSharedMemorySize, GSMEM3_B);
    cudaFuncSetAttribute(gemm_mma<1>, cudaFuncAttributeMaxDynamicSharedMemorySize, GSMEM1_B);
    cudaFuncSetAttribute(fused_attn, cudaFuncAttributeMaxDynamicSharedMemorySize, FS_SMEM);

    float *p_x, *p_v;
    __nv_bfloat16 *p_chi, *p_clo, *p_shi, *p_slo, *p_avh;
    __nv_bfloat16 *p_qh, *p_ql, *p_kh, *p_kl;
    __nv_bfloat16 *p_wqh, *p_wql, *p_wkh, *p_wkl, *p_wvh, *p_wvl, *p_woh;
    cudaGetSymbolAddress((void**)&p_v,   g_v);
    cudaGetSymbolAddress((void**)&p_x,   g_x);
    cudaGetSymbolAddress((void**)&p_chi, g_c_hi);
    cudaGetSymbolAddress((void**)&p_clo, g_c_lo);
    cudaGetSymbolAddress((void**)&p_shi, g_s_hi);
    cudaGetSymbolAddress((void**)&p_slo, g_s_lo);
    cudaGetSymbolAddress((void**)&p_qh,  g_qh);
    cudaGetSymbolAddress((void**)&p_ql,  g_ql);
    cudaGetSymbolAddress((void**)&p_kh,  g_kh);
    cudaGetSymbolAddress((void**)&p_kl,  g_kl);
    cudaGetSymbolAddress((void**)&p_avh, g_avh);
    cudaGetSymbolAddress((void**)&p_wqh, g_wqt_hi);
    cudaGetSymbolAddress((void**)&p_wql, g_wqt_lo);
    cudaGetSymbolAddress((void**)&p_wkh, g_wkt_hi);
    cudaGetSymbolAddress((void**)&p_wkl, g_wkt_lo);
    cudaGetSymbolAddress((void**)&p_wvh, g_wvt_hi);
    cudaGetSymbolAddress((void**)&p_wvl, g_wvt_lo);
    cudaGetSymbolAddress((void**)&p_woh, g_wot_hi);

    // 0) splits
    split_kernel<<<(B_ * NC_ * CD_ / 4 + 255) / 256, 256>>>(
        (const float4*)content, (uint2*)p_chi, (uint2*)p_clo, B_ * NC_ * CD_ / 4);
    split_kernel<<<(B_ * NS_ * SD_ / 4 + 255) / 256, 256>>>(
        (const float4*)style, (uint2*)p_shi, (uint2*)p_slo, B_ * NS_ * SD_ / 4);
    tsplit_kernel<<<dim3(32, 32), dim3(32, 8)>>>(Wq, p_wqh, p_wql, CD_, INNER_);
    tsplit_kernel<<<dim3(32, 24), dim3(32, 8)>>>(Wk, p_wkh, p_wkl, SD_, INNER_);
    tsplit_kernel<<<dim3(32, 24), dim3(32, 8)>>>(Wv, p_wvh, p_wvl, SD_, INNER_);
    // Wo: only hi needed (1-term O-proj). lo lands in g_ql, overwritten by Q proj after.
    tsplit_kernel<<<dim3(32, 32), dim3(32, 8)>>>(Wo, p_woh, p_ql /*discard*/, INNER_, CD_);

    // 1) Q proj -> bf16 hi/lo (pre-scaled 1/8)
    gemm_mma<3><<<dim3(INNER_ / 128, B_ * NC_ / 128), 256, GSMEM3_B>>>(
        p_chi, p_clo, p_wqh, p_wql, nullptr, p_qh, p_ql,
        B_ * NC_, INNER_, CD_, nullptr, nullptr, 0.125f);
    // 2) K proj -> bf16 hi/lo
    gemm_mma<3><<<dim3(INNER_ / 128, B_ * NS_ / 128), 256, GSMEM3_B>>>(
        p_shi, p_slo, p_wkh, p_wkl, nullptr, p_kh, p_kl,
        B_ * NS_, INNER_, SD_, nullptr, nullptr, 1.0f);
    // 3) V proj -> fp32, then per-head transpose to fp16
    gemm_mma<3><<<dim3(INNER_ / 128, B_ * NS_ / 128), 256, GSMEM3_B>>>(
        p_shi, p_slo, p_wvh, p_wvl, p_v, nullptr, nullptr,
        B_ * NS_, INNER_, SD_, nullptr, nullptr, 1.0f);
    vtsplit_kernel<<<dim3(32, 32, B_), dim3(32, 8)>>>();

    // 4) FUSED scores + softmax + P·V
    fused_attn<<<dim3(NC_ / 32, B_ * H_), 256, FS_SMEM>>>();
    // 5) head-mean -> second output
    attn_mean_kernel<<<B_ * NC_ * NS_ / 4 / 256, 256>>>(out_attn);
    // 6) O proj (1-term) + bias + residual
    gemm_mma<1><<<dim3(CD_ / 128, B_ * NC_ / 128), 256, GSMEM1_B>>>(
        p_avh, nullptr, p_woh, nullptr, p_x, nullptr, nullptr,
        B_ * NC_, CD_, INNER_, bo, content, 1.0f);
    // 7) LayerNorm -> first output
    ln_kernel<<<B_ * NC_, 256>>>(gamma, beta, out);
}

// round 16
// speedup vs baseline: 1.3263x; 1.1660x over previous
#include <cuda_runtime.h>
#include <cuda_bf16.h>
#include <cuda_fp16.h>
#include <math.h>
#include <stdint.h>

#define B_    4
#define NC_   4096
#define NS_   1024
#define CD_   1024
#define SD_   768
#define H_    16
#define D_    64
#define INNER_ 1024
#define LN_EPS 1e-5f

// ---------------- static device scratch (fp16 splits, 2-term) ----------------
__device__ float g_attn[(size_t)B_ * H_ * NC_ * NS_];   // probs fp16 rows (2048 B/row used)
__device__ float g_x[(size_t)B_ * NC_ * CD_];
__device__ float g_v[(size_t)B_ * NS_ * INNER_];

__device__ __half g_c_hi[(size_t)B_ * NC_ * CD_];
__device__ __half g_c_lo[(size_t)B_ * NC_ * CD_];
__device__ __half g_s_hi[(size_t)B_ * NS_ * SD_];
__device__ __half g_s_lo[(size_t)B_ * NS_ * SD_];
__device__ __half g_qh[(size_t)B_ * NC_ * INNER_];     // Q (pre-scaled 1/8) hi/lo
__device__ __half g_ql[(size_t)B_ * NC_ * INNER_];
__device__ __half g_kh[(size_t)B_ * NS_ * INNER_];     // K hi only
__device__ __half g_vth[(size_t)B_ * INNER_ * NS_];    // V^T per head, fp16
__device__ __half g_avh[(size_t)B_ * NC_ * INNER_];    // attended, fp16

__device__ __half g_wqt[INNER_ * CD_];                 // weights hi only
__device__ __half g_wkt[INNER_ * SD_];
__device__ __half g_wvt[INNER_ * SD_];
__device__ __half g_wot[CD_ * INNER_];

// ================= helpers =================
__device__ __forceinline__ uint32_t smem_u32(const void* p) {
    uint32_t a;
    asm("{ .reg .u64 t; cvta.to.shared.u64 t, %1; cvt.u32.u64 %0, t; }" : "=r"(a) : "l"(p));
    return a;
}
__device__ __forceinline__ void ldsm_x4(uint32_t* f, uint32_t addr) {
    asm volatile("ldmatrix.sync.aligned.m8n8.x4.shared.b16 {%0,%1,%2,%3}, [%4];"
                 : "=r"(f[0]), "=r"(f[1]), "=r"(f[2]), "=r"(f[3]) : "r"(addr));
}
__device__ __forceinline__ void ldsm_x2(uint32_t* f, uint32_t addr) {
    asm volatile("ldmatrix.sync.aligned.m8n8.x2.shared.b16 {%0,%1}, [%2];"
                 : "=r"(f[0]), "=r"(f[1]) : "r"(addr));
}
__device__ __forceinline__ void mma_f16(float* c, const uint32_t* a, const uint32_t* b) {
    asm volatile("mma.sync.aligned.m16n8k16.row.col.f32.f16.f16.f32 "
                 "{%0,%1,%2,%3}, {%4,%5,%6,%7}, {%8,%9}, {%0,%1,%2,%3};"
                 : "+f"(c[0]), "+f"(c[1]), "+f"(c[2]), "+f"(c[3])
                 : "r"(a[0]), "r"(a[1]), "r"(a[2]), "r"(a[3]), "r"(b[0]), "r"(b[1]));
}
__device__ __forceinline__ void splith2(float x, float y, uint32_t& hp, uint32_t& lp) {
    __half hx = __float2half_rn(x), hy = __float2half_rn(y);
    hp = ((uint32_t)*(uint16_t*)&hy << 16) | *(uint16_t*)&hx;
    __half lx = __float2half_rn(x - __half2float(hx));
    __half ly = __float2half_rn(y - __half2float(hy));
    lp = ((uint32_t)*(uint16_t*)&ly << 16) | *(uint16_t*)&lx;
}
__device__ __forceinline__ uint32_t packh2(float x, float y) {
    __half2 t = __floats2half2_rn(x, y);
    return *(uint32_t*)&t;
}

#define CP16(dst, src)  asm volatile("cp.async.cg.shared.global [%0], [%1], 16;" :: "r"(dst), "l"(src))
#define CP_COMMIT()     asm volatile("cp.async.commit_group;" ::: "memory")
#define CP_WAIT0()      asm volatile("cp.async.wait_group 0;" ::: "memory")
#define CP_WAIT1()      asm volatile("cp.async.wait_group 1;" ::: "memory")

// ================================================================
// fp16 2-term GEMM: C = (Ah+Al)[M,K] @ Bh[N,K]^T  (TERMS=2)
//                or Ah @ Bh^T                      (TERMS=1)
// 128x128 tile, BK=32, 256 thr = 8 warps, cp.async dbuf (2 CTAs/SM).
// Byte layout identical to the validated bf16 kernel (80-B rows).
// ================================================================
#define TILE_B    10240
#define GSMEM2_B  (2 * 3 * TILE_B)   // 61440
#define GSMEM1_B  (2 * 2 * TILE_B)   // 40960

template <int TERMS>
__global__ void __launch_bounds__(256, 2) gemm_mma(
    const __half* __restrict__ Ah, const __half* __restrict__ Al,
    const __half* __restrict__ Bh,
    float* __restrict__ C, __half* __restrict__ Oh, __half* __restrict__ Ol,
    int M, int N, int K,
    const float* __restrict__ bias, const float* __restrict__ resid, float alpha)
{
    extern __shared__ char sm[];
    const int tid = threadIdx.x;
    const int lane = tid & 31;
    const int wid = tid >> 5;
    const int bm = blockIdx.y * 128;
    const int bn = blockIdx.x * 128;
    const int nch = K >> 5;
    const int NT = (TERMS == 2) ? 3 : 2;       // tiles: Ah[,Al],Bh
    const int NIT = NT * 2;                    // (NT*512)/256
    const int BUFT = NT * TILE_B;
    const int BOFS = (TERMS == 2) ? 2 * TILE_B : TILE_B;  // Bh tile offset

    const int wm = (wid >> 2) * 64;
    const int wn = (wid & 3) * 32;

    const uint32_t sA = smem_u32(sm);
    const uint32_t a_off = (uint32_t)(lane & 15) * 80 + (uint32_t)(lane >> 4) * 16;
    const uint32_t b_off = (uint32_t)(lane & 7) * 80 + (uint32_t)((lane >> 3) & 1) * 16;

    float acc[4][4][4];
#pragma unroll
    for (int mt = 0; mt < 4; mt++)
#pragma unroll
        for (int nt = 0; nt < 4; nt++)
#pragma unroll
            for (int r = 0; r < 4; r++) acc[mt][nt][r] = 0.f;

    auto issue = [&](int c, int buf) {
        const int ko = c << 5;
#pragma unroll
        for (int it = 0; it < NIT; it++) {
            const int idx = (it << 8) + tid;
            const int t = idx >> 9;            // 0..NT-1
            const int r = (idx >> 2) & 127;
            const int s = idx & 3;
            const __half* src = (TERMS == 2)
                ? ((t == 0) ? Ah : (t == 1) ? Al : Bh)
                : ((t == 0) ? Ah : Bh);
            const bool isA = (TERMS == 2) ? (t < 2) : (t == 0);
            const int rb = isA ? bm : bn;
            CP16(sA + buf * BUFT + t * TILE_B + r * 80 + s * 16,
                 src + (size_t)(rb + r) * K + ko + s * 8);
        }
        CP_COMMIT();
    };

    issue(0, 0);

    for (int c = 0; c < nch; c++) {
        if (c + 1 < nch) { issue(c + 1, (c + 1) & 1); CP_WAIT1(); }
        else             { CP_WAIT0(); }
        __syncthreads();

        const uint32_t base = sA + (uint32_t)(c & 1) * BUFT;
#pragma unroll
        for (int kk = 0; kk < 2; kk++) {
            const uint32_t ko = kk * 32;
            uint32_t bh[4][2];
#pragma unroll
            for (int nt = 0; nt < 4; nt++)
                ldsm_x2(bh[nt], base + BOFS + (uint32_t)(wn + nt * 8) * 80 + b_off + ko);
#pragma unroll
            for (int mt = 0; mt < 4; mt++) {
                uint32_t ah[4], al[4];
                ldsm_x4(ah, base + (uint32_t)(wm + mt * 16) * 80 + a_off + ko);
                if (TERMS == 2)
                    ldsm_x4(al, base + TILE_B + (uint32_t)(wm + mt * 16) * 80 + a_off + ko);
#pragma unroll
                for (int nt = 0; nt < 4; nt++) {
                    mma_f16(acc[mt][nt], ah, bh[nt]);
                    if (TERMS == 2) mma_f16(acc[mt][nt], al, bh[nt]);
                }
            }
        }
        __syncthreads();
    }

#pragma unroll
    for (int mt = 0; mt < 4; mt++) {
        const int row0 = bm + wm + mt * 16 + (lane >> 2);
#pragma unroll
        for (int nt = 0; nt < 4; nt++) {
            const int col = bn + wn + nt * 8 + (lane & 3) * 2;
#pragma unroll
            for (int half = 0; half < 2; half++) {
                const int row = row0 + half * 8;
                float vx = acc[mt][nt][half * 2] * alpha;
                float vy = acc[mt][nt][half * 2 + 1] * alpha;
                if (Oh) {
                    uint32_t hp, lp;
                    splith2(vx, vy, hp, lp);
                    *(uint32_t*)(Oh + (size_t)row * N + col) = hp;
                    if (Ol) *(uint32_t*)(Ol + (size_t)row * N + col) = lp;
                } else {
                    if (bias) { vx += bias[col]; vy += bias[col + 1]; }
                    if (resid) {
                        float2 t = *(const float2*)(resid + (size_t)row * N + col);
                        vx += t.x; vy += t.y;
                    }
                    *(float2*)(C + (size_t)row * N + col) = make_float2(vx, vy);
                }
            }
        }
    }
}

// ================================================================
// FUSED scores + softmax + P·V (fp16, 2-term scores).
// smem: Q 9216 + K dbuf 2x18432 + scores 32x4128 = 178176 B.
// Phase 3: four 256-col V chunks (64 rows x 528 B stride) in K region.
// ================================================================
#define FS_QSP  4608
#define FS_QT   (2 * FS_QSP)
#define FS_KSP  18432
#define FS_SROW 4128
#define FS_SMEM (FS_QT + 2 * FS_KSP + 32 * FS_SROW)   // 178176

__global__ void __launch_bounds__(256, 1) fused_attn()
{
    extern __shared__ char sm[];
    const int tid = threadIdx.x;
    const int lane = tid & 31;
    const int wid = tid >> 5;
    const int z = blockIdx.y;
    const int b = z >> 4;
    const int h = z & 15;
    const int q0 = b * NC_ + blockIdx.x * 32;
    const int kb = b * NS_;

    char* smQ = sm;
    char* smK = sm + FS_QT;
    char* smS = sm + FS_QT + 2 * FS_KSP;
    const uint32_t uQ = smem_u32(smQ);
    const uint32_t uK = smem_u32(smK);
    const uint32_t uS = smem_u32(smS);

    // K chunk (hi only): 128 rows x 64 fp16 = 1024 uint4 items -> 4 iters
    auto issueK = [&](int c, int buf) {
        const int krow = kb + c * 128;
#pragma unroll
        for (int it = 0; it < 4; it++) {
            const int idx = (it << 8) + tid;
            const int r = idx >> 3;
            const int s = idx & 7;
            CP16(uK + buf * FS_KSP + r * 144 + s * 16,
                 g_kh + (size_t)(krow + r) * INNER_ + h * 64 + s * 8);
        }
        CP_COMMIT();
    };

    issueK(0, 0);

    // Q tile (hi/lo): 2 x 32 x 8 = 512 items
#pragma unroll
    for (int it = 0; it < 2; it++) {
        const int idx = (it << 8) + tid;
        const int sp = idx >> 8;
        const int r = (idx >> 3) & 31;
        const int s = idx & 7;
        const __half* src = sp ? g_ql : g_qh;
        uint4 v = *(const uint4*)(src + (size_t)(q0 + r) * INNER_ + h * 64 + s * 8);
        *(uint4*)(smQ + sp * FS_QSP + r * 144 + s * 16) = v;
    }

    const int wm = (wid >> 2) * 16;
    const int wn = (wid & 3) * 32;
    const uint32_t a_off = (uint32_t)(lane & 15) * 144 + (uint32_t)(lane >> 4) * 16;
    const uint32_t b_off = (uint32_t)(lane & 7) * 144 + (uint32_t)((lane >> 3) & 1) * 16;

    // ---- Phase 1: scores (2-term: Qh·Kh + Ql·Kh) ----
    for (int kc = 0; kc < 8; kc++) {
        if (kc + 1 < 8) { issueK(kc + 1, (kc + 1) & 1); CP_WAIT1(); }
        else            { CP_WAIT0(); }
        __syncthreads();

        float acc[4][4];
#pragma unroll
        for (int nt = 0; nt < 4; nt++)
#pragma unroll
            for (int r = 0; r < 4; r++) acc[nt][r] = 0.f;

        const uint32_t kbuf = uK + (uint32_t)(kc & 1) * FS_KSP;
#pragma unroll
        for (int kk = 0; kk < 4; kk++) {
            const uint32_t ko = kk * 32;
            uint32_t ah[4], al[4];
            ldsm_x4(ah, uQ + (uint32_t)wm * 144 + a_off + ko);
            ldsm_x4(al, uQ + FS_QSP + (uint32_t)wm * 144 + a_off + ko);
            uint32_t bh[4][2];
#pragma unroll
            for (int nt = 0; nt < 4; nt++)
                ldsm_x2(bh[nt], kbuf + (uint32_t)(wn + nt * 8) * 144 + b_off + ko);
#pragma unroll
            for (int nt = 0; nt < 4; nt++) {
                mma_f16(acc[nt], ah, bh[nt]);
                mma_f16(acc[nt], al, bh[nt]);
            }
        }
#pragma unroll
        for (int nt = 0; nt < 4; nt++) {
            const int col = kc * 128 + wn + nt * 8 + (lane & 3) * 2;
#pragma unroll
            for (int half = 0; half < 2; half++) {
                const int row = wm + (lane >> 2) + half * 8;
                *(float2*)(smS + row * FS_SROW + col * 4) =
                    make_float2(acc[nt][half * 2], acc[nt][half * 2 + 1]);
            }
        }
        __syncthreads();   // protect buffer kc&1 before next issueK overwrites it
    }

    // ---- Phase 2: softmax; probs fp16 to own smem rows + global ----
    char* gz = (char*)g_attn + (((size_t)z << 12) + (size_t)blockIdx.x * 32) * 2048;
#pragma unroll
    for (int rr = 0; rr < 4; rr++) {
        const int r = wid * 4 + rr;
        char* rb = smS + r * FS_SROW;
        float4 v[8];
#pragma unroll
        for (int it = 0; it < 8; it++) v[it] = *(const float4*)(rb + lane * 16 + it * 512);

        float m = -1e30f;
#pragma unroll
        for (int it = 0; it < 8; it++)
            m = fmaxf(m, fmaxf(fmaxf(v[it].x, v[it].y), fmaxf(v[it].z, v[it].w)));
#pragma unroll
        for (int o = 16; o; o >>= 1) m = fmaxf(m, __shfl_xor_sync(0xffffffffu, m, o));

        float s = 0.f;
#pragma unroll
        for (int it = 0; it < 8; it++) {
            v[it].x = __expf(v[it].x - m); v[it].y = __expf(v[it].y - m);
            v[it].z = __expf(v[it].z - m); v[it].w = __expf(v[it].w - m);
            s += (v[it].x + v[it].y) + (v[it].z + v[it].w);
        }
#pragma unroll
        for (int o = 16; o; o >>= 1) s += __shfl_xor_sync(0xffffffffu, s, o);
        const float inv = 1.f / s;

        char* grow = gz + (size_t)r * 2048;
#pragma unroll
        for (int it = 0; it < 8; it++) {
            uint2 p = make_uint2(packh2(v[it].x * inv, v[it].y * inv),
                                 packh2(v[it].z * inv, v[it].w * inv));
            const int cofs = (it * 128 + lane * 4) * 2;
            *(uint2*)(rb + cofs) = p;
            *(uint2*)(grow + cofs) = p;
        }
    }
    __syncthreads();

    // ---- Phase 3: O = P @ V^T, four 256-col V chunks in K region ----
    const __half* vth = g_vth + (size_t)z * 64 * NS_;
    const int wd = (wid & 3) * 16;
    const uint32_t ap_off = (uint32_t)(lane & 15) * FS_SROW + (uint32_t)(lane >> 4) * 16;
    const uint32_t bv_off = (uint32_t)(lane & 7) * 528 + (uint32_t)((lane >> 3) & 1) * 16;

    float acco[2][4];
#pragma unroll
    for (int nt = 0; nt < 2; nt++)
#pragma unroll
        for (int r = 0; r < 4; r++) acco[nt][r] = 0.f;

#pragma unroll
    for (int c2 = 0; c2 < 4; c2++) {
        // V chunk: 64 rows x 256 fp16 (512 B/row, 528 stride) = 2048 uint4 items
#pragma unroll
        for (int it = 0; it < 8; it++) {
            const int item = (it << 8) + tid;
            const int r = item >> 5;           // 0..63
            const int s = item & 31;           // 0..31 (s*16 <= 496 < 528)
            *(uint4*)(smK + r * 528 + s * 16) =
                *(const uint4*)(vth + (size_t)r * NS_ + c2 * 256 + s * 8);
        }
        __syncthreads();

#pragma unroll
        for (int kc2 = 0; kc2 < 4; kc2++) {
#pragma unroll
            for (int kk = 0; kk < 4; kk++) {
                const uint32_t ko = (uint32_t)(kc2 * 128 + kk * 32);   // <= 480
                uint32_t ah[4];
                ldsm_x4(ah, uS + (uint32_t)wm * FS_SROW + ap_off + (uint32_t)c2 * 512 + ko);
                uint32_t bh[2][2];
#pragma unroll
                for (int nt = 0; nt < 2; nt++)
                    ldsm_x2(bh[nt], uK + (uint32_t)(wd + nt * 8) * 528 + bv_off + ko);
#pragma unroll
                for (int nt = 0; nt < 2; nt++)
                    mma_f16(acco[nt], ah, bh[nt]);
            }
        }
        if (c2 < 3) __syncthreads();   // before next chunk load overwrites smK
    }

    // epilogue: O 32x64 -> g_avh fp16
#pragma unroll
    for (int nt = 0; nt < 2; nt++) {
        const int col = h * 64 + wd + nt * 8 + (lane & 3) * 2;
#pragma unroll
        for (int half = 0; half < 2; half++) {
            const int row = q0 + wm + (lane >> 2) + half * 8;
            *(uint32_t*)(g_avh + (size_t)row * INNER_ + col) =
                packh2(acco[nt][half * 2], acco[nt][half * 2 + 1]);
        }
    }
}

// ================================================================
// attn_mean from fp16 probs (2048 B rows)
// ================================================================
__global__ void attn_mean_kernel(float* __restrict__ out2)
{
    const size_t idx = (size_t)blockIdx.x * 256 + threadIdx.x;
    const size_t e0 = idx << 2;
    const int b = (int)(e0 >> 22);
    const int q = (int)((e0 >> 10) & 4095);
    const int k = (int)(e0 & 1023);
    const __half* pb = (const __half*)g_attn;

    float s0 = 0.f, s1 = 0.f, s2 = 0.f, s3 = 0.f;
#pragma unroll
    for (int h = 0; h < H_; h++) {
        const size_t row = ((size_t)(b * H_ + h) << 12) + q;
        uint2 hv = *(const uint2*)(pb + row * 1024 + k);
        float2 h0 = __half22float2(*(__half2*)&hv.x);
        float2 h1 = __half22float2(*(__half2*)&hv.y);
        s0 += h0.x; s1 += h0.y; s2 += h1.x; s3 += h1.y;
    }
    const float c = 1.0f / 16.0f;
    *(float4*)(out2 + e0) = make_float4(s0 * c, s1 * c, s2 * c, s3 * c);
}

// ================================================================
// fp32 -> fp16 hi/lo split
// ================================================================
__global__ void split_kernel(const float4* __restrict__ in,
                             uint2* __restrict__ oh, uint2* __restrict__ ol, int n4)
{
    const int i = blockIdx.x * 256 + threadIdx.x;
    if (i >= n4) return;
    float4 v = in[i];
    __align__(8) __half h[4], l[4];
    const float f[4] = {v.x, v.y, v.z, v.w};
#pragma unroll
    for (int j = 0; j < 4; j++) {
        h[j] = __float2half_rn(f[j]);
        l[j] = __float2half_rn(f[j] - __half2float(h[j]));
    }
    oh[i] = *(uint2*)h;
    ol[i] = *(uint2*)l;
}

// ================================================================
// Transpose weights: fp32 [R][Ncol] -> fp16 [Ncol][R] (hi only)
// ================================================================
__global__ void tsplit_kernel(const float* __restrict__ in,
                              __half* __restrict__ oh, int R, int Ncol)
{
    __shared__ float t[32][33];
    const int bx = blockIdx.x * 32, by = blockIdx.y * 32;
    const int tx = threadIdx.x, ty = threadIdx.y;
#pragma unroll
    for (int i = 0; i < 32; i += 8)
        t[ty + i][tx] = in[(size_t)(by + ty + i) * Ncol + bx + tx];
    __syncthreads();
#pragma unroll
    for (int i = 0; i < 32; i += 8)
        oh[(size_t)(bx + ty + i) * R + by + tx] = __float2half_rn(t[tx][ty + i]);
}

// ================================================================
// V^T to fp16
// ================================================================
__global__ void vtsplit_kernel()
{
    __shared__ float t[32][33];
    const int b = blockIdx.z;
    const int bx = blockIdx.x * 32;
    const int by = blockIdx.y * 32;
    const int tx = threadIdx.x, ty = threadIdx.y;
    const float* in = g_v + (size_t)b * NS_ * INNER_;
#pragma unroll
    for (int i = 0; i < 32; i += 8)
        t[ty + i][tx] = in[(size_t)(by + ty + i) * INNER_ + bx + tx];
    __syncthreads();
#pragma unroll
    for (int i = 0; i < 32; i += 8) {
        const float v = t[tx][ty + i];
        g_vth[(size_t)(b * 1024 + bx + ty + i) * NS_ + by + tx] = __float2half_rn(v);
    }
}

// ================================================================
// LayerNorm
// ================================================================
__global__ void ln_kernel(const float* __restrict__ gamma,
                          const float* __restrict__ beta,
                          float* __restrict__ out)
{
    __shared__ float reds[9];
    __shared__ float redq[9];
    const size_t row = blockIdx.x;
    const int tid = threadIdx.x;

    float4 x = reinterpret_cast<const float4*>(g_x + row * CD_)[tid];
    float s = x.x + x.y + x.z + x.w;
    float q = x.x * x.x + x.y * x.y + x.z * x.z + x.w * x.w;
#pragma unroll
    for (int o = 16; o; o >>= 1) {
        s += __shfl_xor_sync(0xffffffffu, s, o);
        q += __shfl_xor_sync(0xffffffffu, q, o);
    }
    if ((tid & 31) == 0) { reds[tid >> 5] = s; redq[tid >> 5] = q; }
    __syncthreads();
    if (tid == 0) {
        float ss = 0.f, qq = 0.f;
#pragma unroll
        for (int i = 0; i < 8; i++) { ss += reds[i]; qq += redq[i]; }
        reds[8] = ss; redq[8] = qq;
    }
    __syncthreads();
    const float mu = reds[8] * (1.0f / 1024.0f);
    const float var = redq[8] * (1.0f / 1024.0f) - mu * mu;
    const float rstd = rsqrtf(var + LN_EPS);

    float4 g = reinterpret_cast<const float4*>(gamma)[tid];
    float4 bb = reinterpret_cast<const float4*>(beta)[tid];
    float4 r;
    r.x = (x.x - mu) * rstd * g.x + bb.x;
    r.y = (x.y - mu) * rstd * g.y + bb.y;
    r.z = (x.z - mu) * rstd * g.z + bb.z;
    r.w = (x.w - mu) * rstd * g.w + bb.w;
    reinterpret_cast<float4*>(out + row * CD_)[tid] = r;
}

// ================================================================
extern "C" void kernel_launch(void* const* d_in, const int* in_sizes, int n_in,
                              void* d_out, int out_size)
{
    const float* content = (const float*)d_in[0];
    const float* style   = (const float*)d_in[1];
    const float* Wq      = (const float*)d_in[2];
    const float* Wk      = (const float*)d_in[3];
    const float* Wv      = (const float*)d_in[4];
    const float* Wo      = (const float*)d_in[5];
    const float* bo      = (const float*)d_in[6];
    const float* gamma   = (const float*)d_in[7];
    const float* beta    = (const float*)d_in[8];
    float* out = (float*)d_out;
    float* out_attn = out + (size_t)B_ * NC_ * CD_;

    cudaFuncSetAttribute(gemm_mma<2>, cudaFuncAttributeMaxDynamicSharedMemorySize, GSMEM2_B);
    cudaFuncSetAttribute(gemm_mma<1>, cudaFuncAttributeMaxDynamicSharedMemorySize, GSMEM1_B);
    cudaFuncSetAttribute(fused_attn, cudaFuncAttributeMaxDynamicSharedMemorySize, FS_SMEM);

    float *p_x, *p_v;
    __half *p_chi, *p_clo, *p_shi, *p_slo, *p_avh;
    __half *p_qh, *p_ql, *p_kh;
    __half *p_wq, *p_wk, *p_wv, *p_wo;
    cudaGetSymbolAddress((void**)&p_v,   g_v);
    cudaGetSymbolAddress((void**)&p_x,   g_x);
    cudaGetSymbolAddress((void**)&p_chi, g_c_hi);
    cudaGetSymbolAddress((void**)&p_clo, g_c_lo);
    cudaGetSymbolAddress((void**)&p_shi, g_s_hi);
    cudaGetSymbolAddress((void**)&p_slo, g_s_lo);
    cudaGetSymbolAddress((void**)&p_qh,  g_qh);
    cudaGetSymbolAddress((void**)&p_ql,  g_ql);
    cudaGetSymbolAddress((void**)&p_kh,  g_kh);
    cudaGetSymbolAddress((void**)&p_avh, g_avh);
    cudaGetSymbolAddress((void**)&p_wq,  g_wqt);
    cudaGetSymbolAddress((void**)&p_wk,  g_wkt);
    cudaGetSymbolAddress((void**)&p_wv,  g_wvt);
    cudaGetSymbolAddress((void**)&p_wo,  g_wot);

    // 0) splits (activations hi/lo, weights hi only)
    split_kernel<<<(B_ * NC_ * CD_ / 4 + 255) / 256, 256>>>(
        (const float4*)content, (uint2*)p_chi, (uint2*)p_clo, B_ * NC_ * CD_ / 4);
    split_kernel<<<(B_ * NS_ * SD_ / 4 + 255) / 256, 256>>>(
        (const float4*)style, (uint2*)p_shi, (uint2*)p_slo, B_ * NS_ * SD_ / 4);
    tsplit_kernel<<<dim3(32, 32), dim3(32, 8)>>>(Wq, p_wq, CD_, INNER_);
    tsplit_kernel<<<dim3(32, 24), dim3(32, 8)>>>(Wk, p_wk, SD_, INNER_);
    tsplit_kernel<<<dim3(32, 24), dim3(32, 8)>>>(Wv, p_wv, SD_, INNER_);
    tsplit_kernel<<<dim3(32, 32), dim3(32, 8)>>>(Wo, p_wo, INNER_, CD_);

    // 1) Q proj -> fp16 hi/lo (pre-scaled 1/8)
    gemm_mma<2><<<dim3(INNER_ / 128, B_ * NC_ / 128), 256, GSMEM2_B>>>(
        p_chi, p_clo, p_wq, nullptr, p_qh, p_ql,
        B_ * NC_, INNER_, CD_, nullptr, nullptr, 0.125f);
    // 2) K proj -> fp16 hi only
    gemm_mma<2><<<dim3(INNER_ / 128, B_ * NS_ / 128), 256, GSMEM2_B>>>(
        p_shi, p_slo, p_wk, nullptr, p_kh, nullptr,
        B_ * NS_, INNER_, SD_, nullptr, nullptr, 1.0f);
    // 3) V proj -> fp32, then per-head transpose to fp16
    gemm_mma<2><<<dim3(INNER_ / 128, B_ * NS_ / 128), 256, GSMEM2_B>>>(
        p_shi, p_slo, p_wv, p_v, nullptr, nullptr,
        B_ * NS_, INNER_, SD_, nullptr, nullptr, 1.0f);
    vtsplit_kernel<<<dim3(32, 32, B_), dim3(32, 8)>>>();

    // 4) FUSED scores + softmax + P·V
    fused_attn<<<dim3(NC_ / 32, B_ * H_), 256, FS_SMEM>>>();
    // 5) head-mean -> second output
    attn_mean_kernel<<<B_ * NC_ * NS_ / 4 / 256, 256>>>(out_attn);
    // 6) O proj (1-term) + bias + residual
    gemm_mma<1><<<dim3(CD_ / 128, B_ * NC_ / 128), 256, GSMEM1_B>>>(
        p_avh, nullptr, p_wo, p_x, nullptr, nullptr,
        B_ * NC_, CD_, INNER_, bo, content, 1.0f);
    // 7) LayerNorm -> first output
    ln_kernel<<<B_ * NC_, 256>>>(gamma, beta, out);
}

// round 17
// speedup vs baseline: 1.5194x; 1.1456x over previous
#include <cuda_runtime.h>
#include <cuda_fp16.h>
#include <math.h>
#include <stdint.h>

#define B_    4
#define NC_   4096
#define NS_   1024
#define CD_   1024
#define SD_   768
#define H_    16
#define D_    64
#define INNER_ 1024
#define LN_EPS 1e-5f

// ---------------- static device scratch (pure fp16, 1-term) ----------------
__device__ float g_attn[(size_t)B_ * H_ * NC_ * NS_];   // probs fp16 rows (2048 B/row used)
__device__ float g_x[(size_t)B_ * NC_ * CD_];
__device__ float g_v[(size_t)B_ * NS_ * INNER_];

__device__ __half g_c[(size_t)B_ * NC_ * CD_];          // content fp16
__device__ __half g_s[(size_t)B_ * NS_ * SD_];          // style fp16
__device__ __half g_qh[(size_t)B_ * NC_ * INNER_];      // Q (pre-scaled 1/8) fp16
__device__ __half g_kh[(size_t)B_ * NS_ * INNER_];      // K fp16
__device__ __half g_vth[(size_t)B_ * INNER_ * NS_];     // V^T per head, fp16
__device__ __half g_avh[(size_t)B_ * NC_ * INNER_];     // attended, fp16

__device__ __half g_wqt[INNER_ * CD_];
__device__ __half g_wkt[INNER_ * SD_];
__device__ __half g_wvt[INNER_ * SD_];
__device__ __half g_wot[CD_ * INNER_];

// ================= helpers =================
__device__ __forceinline__ uint32_t smem_u32(const void* p) {
    uint32_t a;
    asm("{ .reg .u64 t; cvta.to.shared.u64 t, %1; cvt.u32.u64 %0, t; }" : "=r"(a) : "l"(p));
    return a;
}
__device__ __forceinline__ void ldsm_x4(uint32_t* f, uint32_t addr) {
    asm volatile("ldmatrix.sync.aligned.m8n8.x4.shared.b16 {%0,%1,%2,%3}, [%4];"
                 : "=r"(f[0]), "=r"(f[1]), "=r"(f[2]), "=r"(f[3]) : "r"(addr));
}
__device__ __forceinline__ void ldsm_x2(uint32_t* f, uint32_t addr) {
    asm volatile("ldmatrix.sync.aligned.m8n8.x2.shared.b16 {%0,%1}, [%2];"
                 : "=r"(f[0]), "=r"(f[1]) : "r"(addr));
}
__device__ __forceinline__ void mma_f16(float* c, const uint32_t* a, const uint32_t* b) {
    asm volatile("mma.sync.aligned.m16n8k16.row.col.f32.f16.f16.f32 "
                 "{%0,%1,%2,%3}, {%4,%5,%6,%7}, {%8,%9}, {%0,%1,%2,%3};"
                 : "+f"(c[0]), "+f"(c[1]), "+f"(c[2]), "+f"(c[3])
                 : "r"(a[0]), "r"(a[1]), "r"(a[2]), "r"(a[3]), "r"(b[0]), "r"(b[1]));
}
__device__ __forceinline__ uint32_t packh2(float x, float y) {
    __half2 t = __floats2half2_rn(x, y);
    return *(uint32_t*)&t;
}

#define CP16(dst, src)  asm volatile("cp.async.cg.shared.global [%0], [%1], 16;" :: "r"(dst), "l"(src))
#define CP_COMMIT()     asm volatile("cp.async.commit_group;" ::: "memory")
#define CP_WAIT0()      asm volatile("cp.async.wait_group 0;" ::: "memory")
#define CP_WAIT1()      asm volatile("cp.async.wait_group 1;" ::: "memory")

// ================================================================
// fp16 1-term GEMM: C = Ah[M,K] @ Bh[N,K]^T
// 128x128 tile, BK=32, 256 thr = 8 warps, cp.async dbuf, 2 CTAs/SM.
// (validated R16 TERMS=1 path)
// ================================================================
#define TILE_B    10240
#define GSMEM_B   (2 * 2 * TILE_B)   // 40960

__global__ void __launch_bounds__(256, 2) gemm_mma(
    const __half* __restrict__ Ah, const __half* __restrict__ Bh,
    float* __restrict__ C, __half* __restrict__ Oh,
    int M, int N, int K,
    const float* __restrict__ bias, const float* __restrict__ resid, float alpha)
{
    extern __shared__ char sm[];
    const int tid = threadIdx.x;
    const int lane = tid & 31;
    const int wid = tid >> 5;
    const int bm = blockIdx.y * 128;
    const int bn = blockIdx.x * 128;
    const int nch = K >> 5;

    const int wm = (wid >> 2) * 64;
    const int wn = (wid & 3) * 32;

    const uint32_t sA = smem_u32(sm);
    const uint32_t a_off = (uint32_t)(lane & 15) * 80 + (uint32_t)(lane >> 4) * 16;
    const uint32_t b_off = (uint32_t)(lane & 7) * 80 + (uint32_t)((lane >> 3) & 1) * 16;

    float acc[4][4][4];
#pragma unroll
    for (int mt = 0; mt < 4; mt++)
#pragma unroll
        for (int nt = 0; nt < 4; nt++)
#pragma unroll
            for (int r = 0; r < 4; r++) acc[mt][nt][r] = 0.f;

    auto issue = [&](int c, int buf) {
        const int ko = c << 5;
#pragma unroll
        for (int it = 0; it < 4; it++) {
            const int idx = (it << 8) + tid;
            const int t = idx >> 9;            // 0 = Ah, 1 = Bh
            const int r = (idx >> 2) & 127;
            const int s = idx & 3;
            const __half* src = (t == 0) ? Ah : Bh;
            const int rb = (t == 0) ? bm : bn;
            CP16(sA + buf * (2 * TILE_B) + t * TILE_B + r * 80 + s * 16,
                 src + (size_t)(rb + r) * K + ko + s * 8);
        }
        CP_COMMIT();
    };

    issue(0, 0);

    for (int c = 0; c < nch; c++) {
        if (c + 1 < nch) { issue(c + 1, (c + 1) & 1); CP_WAIT1(); }
        else             { CP_WAIT0(); }
        __syncthreads();

        const uint32_t base = sA + (uint32_t)(c & 1) * (2 * TILE_B);
#pragma unroll
        for (int kk = 0; kk < 2; kk++) {
            const uint32_t ko = kk * 32;
            uint32_t bh[4][2];
#pragma unroll
            for (int nt = 0; nt < 4; nt++)
                ldsm_x2(bh[nt], base + TILE_B + (uint32_t)(wn + nt * 8) * 80 + b_off + ko);
#pragma unroll
            for (int mt = 0; mt < 4; mt++) {
                uint32_t ah[4];
                ldsm_x4(ah, base + (uint32_t)(wm + mt * 16) * 80 + a_off + ko);
#pragma unroll
                for (int nt = 0; nt < 4; nt++)
                    mma_f16(acc[mt][nt], ah, bh[nt]);
            }
        }
        __syncthreads();
    }

#pragma unroll
    for (int mt = 0; mt < 4; mt++) {
        const int row0 = bm + wm + mt * 16 + (lane >> 2);
#pragma unroll
        for (int nt = 0; nt < 4; nt++) {
            const int col = bn + wn + nt * 8 + (lane & 3) * 2;
#pragma unroll
            for (int half = 0; half < 2; half++) {
                const int row = row0 + half * 8;
                float vx = acc[mt][nt][half * 2] * alpha;
                float vy = acc[mt][nt][half * 2 + 1] * alpha;
                if (Oh) {
                    *(uint32_t*)(Oh + (size_t)row * N + col) = packh2(vx, vy);
                } else {
                    if (bias) { vx += bias[col]; vy += bias[col + 1]; }
                    if (resid) {
                        float2 t = *(const float2*)(resid + (size_t)row * N + col);
                        vx += t.x; vy += t.y;
                    }
                    *(float2*)(C + (size_t)row * N + col) = make_float2(vx, vy);
                }
            }
        }
    }
}

// ================================================================
// FUSED scores + softmax + P·V (pure fp16, 1-term scores).
// smem: Q 4608 + K dbuf 2x18432 + scores 32x4128 = 173568 B.
// ================================================================
#define FS_QT   4608
#define FS_KSP  18432
#define FS_SROW 4128
#define FS_SMEM (FS_QT + 2 * FS_KSP + 32 * FS_SROW)   // 173568

__global__ void __launch_bounds__(256, 1) fused_attn()
{
    extern __shared__ char sm[];
    const int tid = threadIdx.x;
    const int lane = tid & 31;
    const int wid = tid >> 5;
    const int z = blockIdx.y;
    const int b = z >> 4;
    const int h = z & 15;
    const int q0 = b * NC_ + blockIdx.x * 32;
    const int kb = b * NS_;

    char* smQ = sm;
    char* smK = sm + FS_QT;
    char* smS = sm + FS_QT + 2 * FS_KSP;
    const uint32_t uQ = smem_u32(smQ);
    const uint32_t uK = smem_u32(smK);
    const uint32_t uS = smem_u32(smS);

    // K chunk: 128 rows x 64 fp16 = 1024 uint4 items -> 4 iters
    auto issueK = [&](int c, int buf) {
        const int krow = kb + c * 128;
#pragma unroll
        for (int it = 0; it < 4; it++) {
            const int idx = (it << 8) + tid;
            const int r = idx >> 3;
            const int s = idx & 7;
            CP16(uK + buf * FS_KSP + r * 144 + s * 16,
                 g_kh + (size_t)(krow + r) * INNER_ + h * 64 + s * 8);
        }
        CP_COMMIT();
    };

    issueK(0, 0);

    // Q tile (hi only): 32 rows x 8 segs = 256 items, exactly 1 iter
    {
        const int r = tid >> 3;
        const int s = tid & 7;
        uint4 v = *(const uint4*)(g_qh + (size_t)(q0 + r) * INNER_ + h * 64 + s * 8);
        *(uint4*)(smQ + r * 144 + s * 16) = v;
    }

    const int wm = (wid >> 2) * 16;
    const int wn = (wid & 3) * 32;
    const uint32_t a_off = (uint32_t)(lane & 15) * 144 + (uint32_t)(lane >> 4) * 16;
    const uint32_t b_off = (uint32_t)(lane & 7) * 144 + (uint32_t)((lane >> 3) & 1) * 16;

    // ---- Phase 1: scores (1-term) ----
    for (int kc = 0; kc < 8; kc++) {
        if (kc + 1 < 8) { issueK(kc + 1, (kc + 1) & 1); CP_WAIT1(); }
        else            { CP_WAIT0(); }
        __syncthreads();

        float acc[4][4];
#pragma unroll
        for (int nt = 0; nt < 4; nt++)
#pragma unroll
            for (int r = 0; r < 4; r++) acc[nt][r] = 0.f;

        const uint32_t kbuf = uK + (uint32_t)(kc & 1) * FS_KSP;
#pragma unroll
        for (int kk = 0; kk < 4; kk++) {
            const uint32_t ko = kk * 32;
            uint32_t ah[4];
            ldsm_x4(ah, uQ + (uint32_t)wm * 144 + a_off + ko);
            uint32_t bh[4][2];
#pragma unroll
            for (int nt = 0; nt < 4; nt++)
                ldsm_x2(bh[nt], kbuf + (uint32_t)(wn + nt * 8) * 144 + b_off + ko);
#pragma unroll
            for (int nt = 0; nt < 4; nt++)
                mma_f16(acc[nt], ah, bh[nt]);
        }
#pragma unroll
        for (int nt = 0; nt < 4; nt++) {
            const int col = kc * 128 + wn + nt * 8 + (lane & 3) * 2;
#pragma unroll
            for (int half = 0; half < 2; half++) {
                const int row = wm + (lane >> 2) + half * 8;
                *(float2*)(smS + row * FS_SROW + col * 4) =
                    make_float2(acc[nt][half * 2], acc[nt][half * 2 + 1]);
            }
        }
        __syncthreads();   // protect buffer kc&1 before next issueK overwrites it
    }

    // ---- Phase 2: softmax; probs fp16 to own smem rows + global ----
    char* gz = (char*)g_attn + (((size_t)z << 12) + (size_t)blockIdx.x * 32) * 2048;
#pragma unroll
    for (int rr = 0; rr < 4; rr++) {
        const int r = wid * 4 + rr;
        char* rb = smS + r * FS_SROW;
        float4 v[8];
#pragma unroll
        for (int it = 0; it < 8; it++) v[it] = *(const float4*)(rb + lane * 16 + it * 512);

        float m = -1e30f;
#pragma unroll
        for (int it = 0; it < 8; it++)
            m = fmaxf(m, fmaxf(fmaxf(v[it].x, v[it].y), fmaxf(v[it].z, v[it].w)));
#pragma unroll
        for (int o = 16; o; o >>= 1) m = fmaxf(m, __shfl_xor_sync(0xffffffffu, m, o));

        float s = 0.f;
#pragma unroll
        for (int it = 0; it < 8; it++) {
            v[it].x = __expf(v[it].x - m); v[it].y = __expf(v[it].y - m);
            v[it].z = __expf(v[it].z - m); v[it].w = __expf(v[it].w - m);
            s += (v[it].x + v[it].y) + (v[it].z + v[it].w);
        }
#pragma unroll
        for (int o = 16; o; o >>= 1) s += __shfl_xor_sync(0xffffffffu, s, o);
        const float inv = 1.f / s;

        char* grow = gz + (size_t)r * 2048;
#pragma unroll
        for (int it = 0; it < 8; it++) {
            uint2 p = make_uint2(packh2(v[it].x * inv, v[it].y * inv),
                                 packh2(v[it].z * inv, v[it].w * inv));
            const int cofs = (it * 128 + lane * 4) * 2;
            *(uint2*)(rb + cofs) = p;
            *(uint2*)(grow + cofs) = p;
        }
    }
    __syncthreads();

    // ---- Phase 3: O = P @ V^T, four 256-col V chunks in K region ----
    const __half* vth = g_vth + (size_t)z * 64 * NS_;
    const int wd = (wid & 3) * 16;
    const uint32_t ap_off = (uint32_t)(lane & 15) * FS_SROW + (uint32_t)(lane >> 4) * 16;
    const uint32_t bv_off = (uint32_t)(lane & 7) * 528 + (uint32_t)((lane >> 3) & 1) * 16;

    float acco[2][4];
#pragma unroll
    for (int nt = 0; nt < 2; nt++)
#pragma unroll
        for (int r = 0; r < 4; r++) acco[nt][r] = 0.f;

#pragma unroll
    for (int c2 = 0; c2 < 4; c2++) {
        // V chunk: 64 rows x 256 fp16 (512 B/row, 528 stride) = 2048 uint4 items
#pragma unroll
        for (int it = 0; it < 8; it++) {
            const int item = (it << 8) + tid;
            const int r = item >> 5;           // 0..63
            const int s = item & 31;           // 0..31
            *(uint4*)(smK + r * 528 + s * 16) =
                *(const uint4*)(vth + (size_t)r * NS_ + c2 * 256 + s * 8);
        }
        __syncthreads();

#pragma unroll
        for (int kc2 = 0; kc2 < 4; kc2++) {
#pragma unroll
            for (int kk = 0; kk < 4; kk++) {
                const uint32_t ko = (uint32_t)(kc2 * 128 + kk * 32);
                uint32_t ah[4];
                ldsm_x4(ah, uS + (uint32_t)wm * FS_SROW + ap_off + (uint32_t)c2 * 512 + ko);
                uint32_t bh[2][2];
#pragma unroll
                for (int nt = 0; nt < 2; nt++)
                    ldsm_x2(bh[nt], uK + (uint32_t)(wd + nt * 8) * 528 + bv_off + ko);
#pragma unroll
                for (int nt = 0; nt < 2; nt++)
                    mma_f16(acco[nt], ah, bh[nt]);
            }
        }
        if (c2 < 3) __syncthreads();
    }

    // epilogue: O 32x64 -> g_avh fp16
#pragma unroll
    for (int nt = 0; nt < 2; nt++) {
        const int col = h * 64 + wd + nt * 8 + (lane & 3) * 2;
#pragma unroll
        for (int half = 0; half < 2; half++) {
            const int row = q0 + wm + (lane >> 2) + half * 8;
            *(uint32_t*)(g_avh + (size_t)row * INNER_ + col) =
                packh2(acco[nt][half * 2], acco[nt][half * 2 + 1]);
        }
    }
}

// ================================================================
// attn_mean from fp16 probs (2048 B rows)
// ================================================================
__global__ void attn_mean_kernel(float* __restrict__ out2)
{
    const size_t idx = (size_t)blockIdx.x * 256 + threadIdx.x;
    const size_t e0 = idx << 2;
    const int b = (int)(e0 >> 22);
    const int q = (int)((e0 >> 10) & 4095);
    const int k = (int)(e0 & 1023);
    const __half* pb = (const __half*)g_attn;

    float s0 = 0.f, s1 = 0.f, s2 = 0.f, s3 = 0.f;
#pragma unroll
    for (int h = 0; h < H_; h++) {
        const size_t row = ((size_t)(b * H_ + h) << 12) + q;
        uint2 hv = *(const uint2*)(pb + row * 1024 + k);
        float2 h0 = __half22float2(*(__half2*)&hv.x);
        float2 h1 = __half22float2(*(__half2*)&hv.y);
        s0 += h0.x; s1 += h0.y; s2 += h1.x; s3 += h1.y;
    }
    const float c = 1.0f / 16.0f;
    *(float4*)(out2 + e0) = make_float4(s0 * c, s1 * c, s2 * c, s3 * c);
}

// ================================================================
// fp32 -> fp16 convert
// ================================================================
__global__ void convert_kernel(const float4* __restrict__ in,
                               uint2* __restrict__ oh, int n4)
{
    const int i = blockIdx.x * 256 + threadIdx.x;
    if (i >= n4) return;
    float4 v = in[i];
    uint2 r;
    r.x = packh2(v.x, v.y);
    r.y = packh2(v.z, v.w);
    oh[i] = r;
}

// ================================================================
// Transpose weights: fp32 [R][Ncol] -> fp16 [Ncol][R]
// ================================================================
__global__ void tsplit_kernel(const float* __restrict__ in,
                              __half* __restrict__ oh, int R, int Ncol)
{
    __shared__ float t[32][33];
    const int bx = blockIdx.x * 32, by = blockIdx.y * 32;
    const int tx = threadIdx.x, ty = threadIdx.y;
#pragma unroll
    for (int i = 0; i < 32; i += 8)
        t[ty + i][tx] = in[(size_t)(by + ty + i) * Ncol + bx + tx];
    __syncthreads();
#pragma unroll
    for (int i = 0; i < 32; i += 8)
        oh[(size_t)(bx + ty + i) * R + by + tx] = __float2half_rn(t[tx][ty + i]);
}

// ================================================================
// V^T to fp16
// ================================================================
__global__ void vtsplit_kernel()
{
    __shared__ float t[32][33];
    const int b = blockIdx.z;
    const int bx = blockIdx.x * 32;
    const int by = blockIdx.y * 32;
    const int tx = threadIdx.x, ty = threadIdx.y;
    const float* in = g_v + (size_t)b * NS_ * INNER_;
#pragma unroll
    for (int i = 0; i < 32; i += 8)
        t[ty + i][tx] = in[(size_t)(by + ty + i) * INNER_ + bx + tx];
    __syncthreads();
#pragma unroll
    for (int i = 0; i < 32; i += 8) {
        const float v = t[tx][ty + i];
        g_vth[(size_t)(b * 1024 + bx + ty + i) * NS_ + by + tx] = __float2half_rn(v);
    }
}

// ================================================================
// LayerNorm
// ================================================================
__global__ void ln_kernel(const float* __restrict__ gamma,
                          const float* __restrict__ beta,
                          float* __restrict__ out)
{
    __shared__ float reds[9];
    __shared__ float redq[9];
    const size_t row = blockIdx.x;
    const int tid = threadIdx.x;

    float4 x = reinterpret_cast<const float4*>(g_x + row * CD_)[tid];
    float s = x.x + x.y + x.z + x.w;
    float q = x.x * x.x + x.y * x.y + x.z * x.z + x.w * x.w;
#pragma unroll
    for (int o = 16; o; o >>= 1) {
        s += __shfl_xor_sync(0xffffffffu, s, o);
        q += __shfl_xor_sync(0xffffffffu, q, o);
    }
    if ((tid & 31) == 0) { reds[tid >> 5] = s; redq[tid >> 5] = q; }
    __syncthreads();
    if (tid == 0) {
        float ss = 0.f, qq = 0.f;
#pragma unroll
        for (int i = 0; i < 8; i++) { ss += reds[i]; qq += redq[i]; }
        reds[8] = ss; redq[8] = qq;
    }
    __syncthreads();
    const float mu = reds[8] * (1.0f / 1024.0f);
    const float var = redq[8] * (1.0f / 1024.0f) - mu * mu;
    const float rstd = rsqrtf(var + LN_EPS);

    float4 g = reinterpret_cast<const float4*>(gamma)[tid];
    float4 bb = reinterpret_cast<const float4*>(beta)[tid];
    float4 r;
    r.x = (x.x - mu) * rstd * g.x + bb.x;
    r.y = (x.y - mu) * rstd * g.y + bb.y;
    r.z = (x.z - mu) * rstd * g.z + bb.z;
    r.w = (x.w - mu) * rstd * g.w + bb.w;
    reinterpret_cast<float4*>(out + row * CD_)[tid] = r;
}

// ================================================================
extern "C" void kernel_launch(void* const* d_in, const int* in_sizes, int n_in,
                              void* d_out, int out_size)
{
    const float* content = (const float*)d_in[0];
    const float* style   = (const float*)d_in[1];
    const float* Wq      = (const float*)d_in[2];
    const float* Wk      = (const float*)d_in[3];
    const float* Wv      = (const float*)d_in[4];
    const float* Wo      = (const float*)d_in[5];
    const float* bo      = (const float*)d_in[6];
    const float* gamma   = (const float*)d_in[7];
    const float* beta    = (const float*)d_in[8];
    float* out = (float*)d_out;
    float* out_attn = out + (size_t)B_ * NC_ * CD_;

    cudaFuncSetAttribute(gemm_mma, cudaFuncAttributeMaxDynamicSharedMemorySize, GSMEM_B);
    cudaFuncSetAttribute(fused_attn, cudaFuncAttributeMaxDynamicSharedMemorySize, FS_SMEM);

    float *p_x, *p_v;
    __half *p_c, *p_s, *p_qh, *p_kh, *p_avh;
    __half *p_wq, *p_wk, *p_wv, *p_wo;
    cudaGetSymbolAddress((void**)&p_v,   g_v);
    cudaGetSymbolAddress((void**)&p_x,   g_x);
    cudaGetSymbolAddress((void**)&p_c,   g_c);
    cudaGetSymbolAddress((void**)&p_s,   g_s);
    cudaGetSymbolAddress((void**)&p_qh,  g_qh);
    cudaGetSymbolAddress((void**)&p_kh,  g_kh);
    cudaGetSymbolAddress((void**)&p_avh, g_avh);
    cudaGetSymbolAddress((void**)&p_wq,  g_wqt);
    cudaGetSymbolAddress((void**)&p_wk,  g_wkt);
    cudaGetSymbolAddress((void**)&p_wv,  g_wvt);
    cudaGetSymbolAddress((void**)&p_wo,  g_wot);

    // 0) converts + weight transposes (all fp16, hi only)
    convert_kernel<<<(B_ * NC_ * CD_ / 4 + 255) / 256, 256>>>(
        (const float4*)content, (uint2*)p_c, B_ * NC_ * CD_ / 4);
    convert_kernel<<<(B_ * NS_ * SD_ / 4 + 255) / 256, 256>>>(
        (const float4*)style, (uint2*)p_s, B_ * NS_ * SD_ / 4);
    tsplit_kernel<<<dim3(32, 32), dim3(32, 8)>>>(Wq, p_wq, CD_, INNER_);
    tsplit_kernel<<<dim3(32, 24), dim3(32, 8)>>>(Wk, p_wk, SD_, INNER_);
    tsplit_kernel<<<dim3(32, 24), dim3(32, 8)>>>(Wv, p_wv, SD_, INNER_);
    tsplit_kernel<<<dim3(32, 32), dim3(32, 8)>>>(Wo, p_wo, INNER_, CD_);

    // 1) Q proj -> fp16 (pre-scaled 1/8)
    gemm_mma<<<dim3(INNER_ / 128, B_ * NC_ / 128), 256, GSMEM_B>>>(
        p_c, p_wq, nullptr, p_qh, B_ * NC_, INNER_, CD_, nullptr, nullptr, 0.125f);
    // 2) K proj -> fp16
    gemm_mma<<<dim3(INNER_ / 128, B_ * NS_ / 128), 256, GSMEM_B>>>(
        p_s, p_wk, nullptr, p_kh, B_ * NS_, INNER_, SD_, nullptr, nullptr, 1.0f);
    // 3) V proj -> fp32, then per-head transpose to fp16
    gemm_mma<<<dim3(INNER_ / 128, B_ * NS_ / 128), 256, GSMEM_B>>>(
        p_s, p_wv, p_v, nullptr, B_ * NS_, INNER_, SD_, nullptr, nullptr, 1.0f);
    vtsplit_kernel<<<dim3(32, 32, B_), dim3(32, 8)>>>();

    // 4) FUSED scores + softmax + P·V
    fused_attn<<<dim3(NC_ / 32, B_ * H_), 256, FS_SMEM>>>();
    // 5) head-mean -> second output
    attn_mean_kernel<<<B_ * NC_ * NS_ / 4 / 256, 256>>>(out_attn);
    // 6) O proj + bias + residual
    gemm_mma<<<dim3(CD_ / 128, B_ * NC_ / 128), 256, GSMEM_B>>>(
        p_avh, p_wo, p_x, nullptr, B_ * NC_, CD_, INNER_, bo, content, 1.0f);
    // 7) LayerNorm -> first output
    ln_kernel<<<B_ * NC_, 256>>>(gamma, beta, out);
}